// round 8
// baseline (speedup 1.0000x reference)
#include <cuda_runtime.h>
#include <math.h>
#include <stdint.h>

#define S_LEN 2048
#define BATCH 2
#define EMB   1024
#define NH    16
#define HD    64
#define MTOT  (BATCH * S_LEN)   // 4096

__device__ float g_q[MTOT * EMB];
__device__ float g_k[MTOT * EMB];
__device__ float g_v[MTOT * EMB];
__device__ float g_att[MTOT * EMB];

__device__ __forceinline__ void mma_tf32(float c[4], uint32_t a0, uint32_t a1,
                                         uint32_t a2, uint32_t a3,
                                         uint32_t b0, uint32_t b1)
{
    asm volatile(
        "mma.sync.aligned.m16n8k8.row.col.f32.tf32.tf32.f32 "
        "{%0,%1,%2,%3}, {%4,%5,%6,%7}, {%8,%9}, {%0,%1,%2,%3};"
        : "+f"(c[0]), "+f"(c[1]), "+f"(c[2]), "+f"(c[3])
        : "r"(a0), "r"(a1), "r"(a2), "r"(a3), "r"(b0), "r"(b1));
}

__device__ __forceinline__ uint32_t tf32_rna(float x)
{
    uint32_t r;
    asm("cvt.rna.tf32.f32 %0, %1;" : "=r"(r) : "f"(x));
    return r;
}
__device__ __forceinline__ void split2(float x, float& hi, float& lo)
{
    hi = __uint_as_float(tf32_rna(x));
    lo = x - hi;
}
__device__ __forceinline__ uint32_t f2b(float x) { return __float_as_uint(x); }

__device__ __forceinline__ void cp16(void* smem, const void* gmem)
{
    uint32_t s = (uint32_t)__cvta_generic_to_shared(smem);
    asm volatile("cp.async.cg.shared.global [%0], [%1], 16;" :: "r"(s), "l"(gmem));
}
#define CP_COMMIT() asm volatile("cp.async.commit_group;" ::: "memory")
#define CP_WAIT1()  asm volatile("cp.async.wait_group 1;" ::: "memory")

// ---------------------------------------------------------------------------
// 3xTF32 GEMM, fragment-order smem (hi/lo pre-split) + ks register pipeline.
// 128x128x32 tile, 256 threads, 8 warps as 2(M) x 4(N), warp tile 64x32.
//
// A fragment store layout: float idx = (mtg*4+ks)*128 + (r*4 + (cq^ks))*4 + j
//   j: 0=A[m0+r][kc] 1=A[m0+8+r][kc] 2=A[m0+r][kc+4] 3=A[m0+8+r][kc+4]
// B fragment store layout: float idx = (ntg*4+ks)*66 + (r*4 + (cq^ks))*2 + j
//   j: 0=B[kc][n0+r] 1=B[kc+4][n0+r]      (66-stride kills store conflicts)
// ---------------------------------------------------------------------------
#define BM 128
#define BN 128
#define BK 32
#define AFSZ (8 * 4 * 128)     // 4096 floats per (hi|lo)
#define BFSZ (16 * 4 * 66)     // 4224 floats per (hi|lo)
#define GEMM_SMEM ((2 * AFSZ + 2 * BFSZ) * 4)   // 66560 B

__device__ __forceinline__ void gemm_tf32_body(
    const float* __restrict__ A, const float* __restrict__ B,
    const float* __restrict__ bias, float* __restrict__ C,
    int M, int N, int K)
{
    extern __shared__ float dsm[];
    float* Ahf = dsm;
    float* Alf = Ahf + AFSZ;
    float* Bhf = Alf + AFSZ;
    float* Blf = Bhf + BFSZ;

    const int tid   = threadIdx.x;
    const int lane  = tid & 31;
    const int warp  = tid >> 5;
    const int warpM = warp >> 2;
    const int warpN = warp & 3;
    const int r     = lane >> 2;
    const int cq    = lane & 3;
    const int tm0   = blockIdx.y * BM;
    const int tn0   = blockIdx.x * BN;

    float acc[4][4][4];
    #pragma unroll
    for (int mt = 0; mt < 4; ++mt)
        #pragma unroll
        for (int nt = 0; nt < 4; ++nt)
            #pragma unroll
            for (int i = 0; i < 4; ++i) acc[mt][nt][i] = 0.f;

    const int arow = tid >> 3;            // 0..31
    const int acol = (tid & 7) * 4;       // 0..28
    const int brow = tid >> 6;            // 0..3
    const int bcol = (tid & 63) * 2;      // 0..126

    const int ks_a    = acol >> 3;
    const int khalf_a = (acol >> 2) & 1;

    float4 a4[4];
    float2 b2[8];

    #pragma unroll
    for (int i = 0; i < 4; ++i)
        a4[i] = *(const float4*)&A[(size_t)(tm0 + arow + i * 32) * K + acol];
    #pragma unroll
    for (int i = 0; i < 8; ++i)
        b2[i] = *(const float2*)&B[(size_t)(brow + i * 4) * N + tn0 + bcol];

    for (int k0 = 0; k0 < K; k0 += BK) {
        // ---- split + store current regs into fragment-order smem ----
        #pragma unroll
        for (int i = 0; i < 4; ++i) {
            int row  = arow + i * 32;
            int mtg  = row >> 4, rr = row & 7, half = (row >> 3) & 1;
            int base = (mtg * 4 + ks_a) * 128 + half + 2 * khalf_a;
            float h, l;
            split2(a4[i].x, h, l);
            { int idx = base + (rr * 4 + (0 ^ ks_a)) * 4; Ahf[idx] = h; Alf[idx] = l; }
            split2(a4[i].y, h, l);
            { int idx = base + (rr * 4 + (1 ^ ks_a)) * 4; Ahf[idx] = h; Alf[idx] = l; }
            split2(a4[i].z, h, l);
            { int idx = base + (rr * 4 + (2 ^ ks_a)) * 4; Ahf[idx] = h; Alf[idx] = l; }
            split2(a4[i].w, h, l);
            { int idx = base + (rr * 4 + (3 ^ ks_a)) * 4; Ahf[idx] = h; Alf[idx] = l; }
        }
        #pragma unroll
        for (int i = 0; i < 8; ++i) {
            int k     = brow + i * 4;
            int cqb   = k & 3;
            int khb   = (k >> 2) & 1;
            int ksb   = k >> 3;
            float h, l;
            split2(b2[i].x, h, l);
            { int n = bcol;     int idx = ((n >> 3) * 4 + ksb) * 66 + ((n & 7) * 4 + (cqb ^ ksb)) * 2 + khb;
              Bhf[idx] = h; Blf[idx] = l; }
            split2(b2[i].y, h, l);
            { int n = bcol + 1; int idx = ((n >> 3) * 4 + ksb) * 66 + ((n & 7) * 4 + (cqb ^ ksb)) * 2 + khb;
              Bhf[idx] = h; Blf[idx] = l; }
        }
        __syncthreads();

        // ---- prefetch next gmem tile into registers ----
        int kn = k0 + BK;
        if (kn < K) {
            #pragma unroll
            for (int i = 0; i < 4; ++i)
                a4[i] = *(const float4*)&A[(size_t)(tm0 + arow + i * 32) * K + kn + acol];
            #pragma unroll
            for (int i = 0; i < 8; ++i)
                b2[i] = *(const float2*)&B[(size_t)(kn + brow + i * 4) * N + tn0 + bcol];
        }

        // ---- MMA with ks-level register double buffering ----
        float4 fAh[2][4], fAl[2][4];
        float2 fBh[2][4], fBl[2][4];

        #define LOAD_FRAGS(ks, buf)                                                        \
        {                                                                                  \
            int slot = (lane & 28) + (cq ^ (ks));                                          \
            _Pragma("unroll")                                                              \
            for (int mt = 0; mt < 4; ++mt) {                                               \
                int gi = ((warpM * 4 + mt) * 4 + (ks)) * 128 + slot * 4;                   \
                fAh[buf][mt] = *(const float4*)&Ahf[gi];                                   \
                fAl[buf][mt] = *(const float4*)&Alf[gi];                                   \
            }                                                                              \
            _Pragma("unroll")                                                              \
            for (int nt = 0; nt < 4; ++nt) {                                               \
                int gi = ((warpN * 4 + nt) * 4 + (ks)) * 66 + slot * 2;                    \
                fBh[buf][nt] = *(const float2*)&Bhf[gi];                                   \
                fBl[buf][nt] = *(const float2*)&Blf[gi];                                   \
            }                                                                              \
        }

        LOAD_FRAGS(0, 0)
        #pragma unroll
        for (int ks = 0; ks < 4; ++ks) {
            int cur = ks & 1;
            if (ks < 3) {
                int nb = cur ^ 1;
                switch (ks) {
                    case 0: LOAD_FRAGS(1, nb) break;
                    case 1: LOAD_FRAGS(2, nb) break;
                    default: LOAD_FRAGS(3, nb) break;
                }
            }
            #pragma unroll
            for (int nt = 0; nt < 4; ++nt) {
                uint32_t bh0 = f2b(fBh[cur][nt].x), bh1 = f2b(fBh[cur][nt].y);
                uint32_t bl0 = f2b(fBl[cur][nt].x), bl1 = f2b(fBl[cur][nt].y);
                #pragma unroll
                for (int mt = 0; mt < 4; ++mt) {
                    uint32_t ah0 = f2b(fAh[cur][mt].x), ah1 = f2b(fAh[cur][mt].y);
                    uint32_t ah2 = f2b(fAh[cur][mt].z), ah3 = f2b(fAh[cur][mt].w);
                    uint32_t al0 = f2b(fAl[cur][mt].x), al1 = f2b(fAl[cur][mt].y);
                    uint32_t al2 = f2b(fAl[cur][mt].z), al3 = f2b(fAl[cur][mt].w);
                    mma_tf32(acc[mt][nt], ah0, ah1, ah2, ah3, bl0, bl1);
                    mma_tf32(acc[mt][nt], al0, al1, al2, al3, bh0, bh1);
                    mma_tf32(acc[mt][nt], ah0, ah1, ah2, ah3, bh0, bh1);
                }
            }
        }
        #undef LOAD_FRAGS
        __syncthreads();
    }

    #pragma unroll
    for (int mt = 0; mt < 4; ++mt) {
        int row = tm0 + warpM * 64 + mt * 16 + r;
        #pragma unroll
        for (int nt = 0; nt < 4; ++nt) {
            int col = tn0 + warpN * 32 + nt * 8 + 2 * cq;
            float b0 = 0.f, b1 = 0.f;
            if (bias) { b0 = bias[col]; b1 = bias[col + 1]; }
            float2 v0 = make_float2(acc[mt][nt][0] + b0, acc[mt][nt][1] + b1);
            float2 v1 = make_float2(acc[mt][nt][2] + b0, acc[mt][nt][3] + b1);
            *(float2*)&C[(size_t)row * N + col]       = v0;
            *(float2*)&C[(size_t)(row + 8) * N + col] = v1;
        }
    }
}

__global__ __launch_bounds__(256) void gemm_tf32_kernel(
    const float* __restrict__ A, const float* __restrict__ B,
    const float* __restrict__ bias, float* __restrict__ C,
    int M, int N, int K)
{
    gemm_tf32_body(A, B, bias, C, M, N, K);
}

__global__ __launch_bounds__(256) void qkv_tf32_kernel(
    const float* __restrict__ x,
    const float* __restrict__ Wq, const float* __restrict__ Wk,
    const float* __restrict__ Wv)
{
    const float* W;
    float* C;
    if (blockIdx.z == 0)      { W = Wq; C = g_q; }
    else if (blockIdx.z == 1) { W = Wk; C = g_k; }
    else                      { W = Wv; C = g_v; }
    gemm_tf32_body(x, W, nullptr, C, MTOT, EMB, EMB);
}

// ---------------------------------------------------------------------------
// 1xTF32 flash attention, 128 queries/CTA (mt=2 per warp), cp.async double
// buffered 64-key K/V tiles. 4 warps; warp w owns rows [w*32, w*32+32).
// ---------------------------------------------------------------------------
#define KSTR 68
#define VSTR 72
#define KSZ (64 * KSTR)
#define VSZ (64 * VSTR)
#define QROWS 128
#define ATTN_SMEM ((2 * (KSZ + VSZ) + QROWS * KSTR) * 4)   // 106496 B

__global__ __launch_bounds__(128) void attn_tf32_kernel()
{
    extern __shared__ float sm[];
    float* Ks[2] = { sm,       sm + KSZ + VSZ };
    float* Vs[2] = { sm + KSZ, sm + 2 * KSZ + VSZ };
    float* QP    = sm + 2 * (KSZ + VSZ);   // [128][KSTR]: Q staging, then P

    const int tid  = threadIdx.x;
    const int lane = tid & 31;
    const int warp = tid >> 5;
    const int r    = lane >> 2;
    const int cq   = lane & 3;
    const int bq   = gridDim.x - 1 - blockIdx.x;  // heavy blocks first
    const int h    = blockIdx.y;
    const int b    = blockIdx.z;
    const int qbase = bq * QROWS;
    const int nkb   = 2 * bq + 2;

    const int lrow = tid >> 4;           // 0..7
    const int lcol = (tid & 15) * 4;     // 0..60

    // Issue K/V tile 0 loads
    #pragma unroll
    for (int i = 0; i < 8; ++i) {
        int row = lrow + i * 8;
        size_t g = ((size_t)(b * S_LEN + row)) * EMB + h * HD + lcol;
        cp16(&Ks[0][row * KSTR + lcol], &g_k[g]);
        cp16(&Vs[0][row * VSTR + lcol], &g_v[g]);
    }
    CP_COMMIT();

    // Stage 128 Q rows, build rna fragments (scaled by 1/8)
    #pragma unroll
    for (int i = 0; i < 16; ++i) {
        int row = lrow + i * 8;
        *(float4*)&QP[row * KSTR + lcol] =
            *(const float4*)&g_q[((size_t)(b * S_LEN + qbase + row)) * EMB + h * HD + lcol];
    }
    __syncthreads();

    uint32_t qf[2][8][4];
    #pragma unroll
    for (int mt = 0; mt < 2; ++mt) {
        int row0 = warp * 32 + mt * 16 + r;
        #pragma unroll
        for (int ks = 0; ks < 8; ++ks) {
            int kc = ks * 8 + cq;
            qf[mt][ks][0] = tf32_rna(QP[row0 * KSTR + kc] * 0.125f);
            qf[mt][ks][1] = tf32_rna(QP[(row0 + 8) * KSTR + kc] * 0.125f);
            qf[mt][ks][2] = tf32_rna(QP[row0 * KSTR + kc + 4] * 0.125f);
            qf[mt][ks][3] = tf32_rna(QP[(row0 + 8) * KSTR + kc + 4] * 0.125f);
        }
    }
    __syncthreads();   // QP now free for P

    float o[2][8][4];
    #pragma unroll
    for (int mt = 0; mt < 2; ++mt)
        #pragma unroll
        for (int nt = 0; nt < 8; ++nt)
            #pragma unroll
            for (int i = 0; i < 4; ++i) o[mt][nt][i] = 0.f;
    float mrw[2][2] = {{-1e30f, -1e30f}, {-1e30f, -1e30f}};
    float lrw[2][2] = {{0.f, 0.f}, {0.f, 0.f}};

    for (int kb = 0; kb < nkb; ++kb) {
        const int cur = kb & 1;
        if (kb + 1 < nkb) {
            float* Kn = Ks[cur ^ 1];
            float* Vn = Vs[cur ^ 1];
            #pragma unroll
            for (int i = 0; i < 8; ++i) {
                int row = lrow + i * 8;
                size_t g = ((size_t)(b * S_LEN + (kb + 1) * 64 + row)) * EMB + h * HD + lcol;
                cp16(&Kn[row * KSTR + lcol], &g_k[g]);
                cp16(&Vn[row * VSTR + lcol], &g_v[g]);
            }
        }
        CP_COMMIT();
        CP_WAIT1();
        __syncthreads();

        const float* Kc = Ks[cur];
        const float* Vc = Vs[cur];

        // S = (Q/8) @ K^T
        float s[2][8][4];
        #pragma unroll
        for (int mt = 0; mt < 2; ++mt)
            #pragma unroll
            for (int nt = 0; nt < 8; ++nt)
                #pragma unroll
                for (int i = 0; i < 4; ++i) s[mt][nt][i] = 0.f;
        #pragma unroll
        for (int ks = 0; ks < 8; ++ks) {
            int kc = ks * 8 + cq;
            #pragma unroll
            for (int nt = 0; nt < 8; ++nt) {
                int krow = nt * 8 + r;
                uint32_t b0 = tf32_rna(Kc[krow * KSTR + kc]);
                uint32_t b1 = tf32_rna(Kc[krow * KSTR + kc + 4]);
                mma_tf32(s[0][nt], qf[0][ks][0], qf[0][ks][1], qf[0][ks][2], qf[0][ks][3], b0, b1);
                mma_tf32(s[1][nt], qf[1][ks][0], qf[1][ks][1], qf[1][ks][2], qf[1][ks][3], b0, b1);
            }
        }

        // Causal mask (only the last two key tiles can clip)
        if (kb * 64 + 63 > qbase) {
            int kg0 = kb * 64;
            #pragma unroll
            for (int mt = 0; mt < 2; ++mt) {
                int qg0 = qbase + warp * 32 + mt * 16 + r;
                int qg1 = qg0 + 8;
                #pragma unroll
                for (int nt = 0; nt < 8; ++nt) {
                    int kg = kg0 + nt * 8 + 2 * cq;
                    if (kg     > qg0) s[mt][nt][0] = -1e30f;
                    if (kg + 1 > qg0) s[mt][nt][1] = -1e30f;
                    if (kg     > qg1) s[mt][nt][2] = -1e30f;
                    if (kg + 1 > qg1) s[mt][nt][3] = -1e30f;
                }
            }
        }

        // Online softmax per mt
        #pragma unroll
        for (int mt = 0; mt < 2; ++mt) {
            float mx0 = -1e30f, mx1 = -1e30f;
            #pragma unroll
            for (int nt = 0; nt < 8; ++nt) {
                mx0 = fmaxf(mx0, fmaxf(s[mt][nt][0], s[mt][nt][1]));
                mx1 = fmaxf(mx1, fmaxf(s[mt][nt][2], s[mt][nt][3]));
            }
            mx0 = fmaxf(mx0, __shfl_xor_sync(0xffffffffu, mx0, 1));
            mx0 = fmaxf(mx0, __shfl_xor_sync(0xffffffffu, mx0, 2));
            mx1 = fmaxf(mx1, __shfl_xor_sync(0xffffffffu, mx1, 1));
            mx1 = fmaxf(mx1, __shfl_xor_sync(0xffffffffu, mx1, 2));
            float mn0 = fmaxf(mrw[mt][0], mx0), mn1 = fmaxf(mrw[mt][1], mx1);
            float sc0 = __expf(mrw[mt][0] - mn0), sc1 = __expf(mrw[mt][1] - mn1);
            mrw[mt][0] = mn0; mrw[mt][1] = mn1;
            float ls0 = 0.f, ls1 = 0.f;
            #pragma unroll
            for (int nt = 0; nt < 8; ++nt) {
                s[mt][nt][0] = __expf(s[mt][nt][0] - mn0);
                s[mt][nt][1] = __expf(s[mt][nt][1] - mn0);
                s[mt][nt][2] = __expf(s[mt][nt][2] - mn1);
                s[mt][nt][3] = __expf(s[mt][nt][3] - mn1);
                ls0 += s[mt][nt][0] + s[mt][nt][1];
                ls1 += s[mt][nt][2] + s[mt][nt][3];
            }
            ls0 += __shfl_xor_sync(0xffffffffu, ls0, 1);
            ls0 += __shfl_xor_sync(0xffffffffu, ls0, 2);
            ls1 += __shfl_xor_sync(0xffffffffu, ls1, 1);
            ls1 += __shfl_xor_sync(0xffffffffu, ls1, 2);
            lrw[mt][0] = lrw[mt][0] * sc0 + ls0;
            lrw[mt][1] = lrw[mt][1] * sc1 + ls1;
            #pragma unroll
            for (int nt = 0; nt < 8; ++nt) {
                o[mt][nt][0] *= sc0; o[mt][nt][1] *= sc0;
                o[mt][nt][2] *= sc1; o[mt][nt][3] *= sc1;
            }
            // P -> smem (per-warp private rows)
            int qr0 = warp * 32 + mt * 16 + r;
            int qr1 = qr0 + 8;
            #pragma unroll
            for (int nt = 0; nt < 8; ++nt) {
                int kc = nt * 8 + 2 * cq;
                QP[qr0 * KSTR + kc]     = s[mt][nt][0];
                QP[qr0 * KSTR + kc + 1] = s[mt][nt][1];
                QP[qr1 * KSTR + kc]     = s[mt][nt][2];
                QP[qr1 * KSTR + kc + 1] = s[mt][nt][3];
            }
        }
        __syncwarp();

        // O += P @ V
        #pragma unroll
        for (int kv = 0; kv < 8; ++kv) {
            int kc = kv * 8 + cq;
            uint32_t p[2][4];
            #pragma unroll
            for (int mt = 0; mt < 2; ++mt) {
                int qr0 = warp * 32 + mt * 16 + r;
                p[mt][0] = tf32_rna(QP[qr0 * KSTR + kc]);
                p[mt][1] = tf32_rna(QP[(qr0 + 8) * KSTR + kc]);
                p[mt][2] = tf32_rna(QP[qr0 * KSTR + kc + 4]);
                p[mt][3] = tf32_rna(QP[(qr0 + 8) * KSTR + kc + 4]);
            }
            #pragma unroll
            for (int nt = 0; nt < 8; ++nt) {
                int ncol = nt * 8 + r;
                uint32_t b0 = tf32_rna(Vc[(kv * 8 + cq) * VSTR + ncol]);
                uint32_t b1 = tf32_rna(Vc[(kv * 8 + cq + 4) * VSTR + ncol]);
                mma_tf32(o[0][nt], p[0][0], p[0][1], p[0][2], p[0][3], b0, b1);
                mma_tf32(o[1][nt], p[1][0], p[1][1], p[1][2], p[1][3], b0, b1);
            }
        }
        __syncthreads();
    }

    #pragma unroll
    for (int mt = 0; mt < 2; ++mt) {
        float inv0 = 1.f / lrw[mt][0], inv1 = 1.f / lrw[mt][1];
        int qr0 = warp * 32 + mt * 16 + r;
        #pragma unroll
        for (int nt = 0; nt < 8; ++nt) {
            int col = h * HD + nt * 8 + 2 * cq;
            float2 v0 = make_float2(o[mt][nt][0] * inv0, o[mt][nt][1] * inv0);
            float2 v1 = make_float2(o[mt][nt][2] * inv1, o[mt][nt][3] * inv1);
            *(float2*)&g_att[((size_t)(b * S_LEN + qbase + qr0)) * EMB + col]     = v0;
            *(float2*)&g_att[((size_t)(b * S_LEN + qbase + qr0 + 8)) * EMB + col] = v1;
        }
    }
}

// ---------------------------------------------------------------------------
extern "C" void kernel_launch(void* const* d_in, const int* in_sizes, int n_in,
                              void* d_out, int out_size)
{
    const float* x  = (const float*)d_in[0];
    const float* Wq = (const float*)d_in[1];
    const float* Wk = (const float*)d_in[2];
    const float* Wv = (const float*)d_in[3];
    const float* Wp = (const float*)d_in[4];
    const float* bp = (const float*)d_in[5];
    float* out = (float*)d_out;

    float* att;
    cudaGetSymbolAddress((void**)&att, g_att);

    cudaFuncSetAttribute(qkv_tf32_kernel,  cudaFuncAttributeMaxDynamicSharedMemorySize, GEMM_SMEM);
    cudaFuncSetAttribute(gemm_tf32_kernel, cudaFuncAttributeMaxDynamicSharedMemorySize, GEMM_SMEM);
    cudaFuncSetAttribute(attn_tf32_kernel, cudaFuncAttributeMaxDynamicSharedMemorySize, ATTN_SMEM);

    dim3 gqkv(EMB / BN, MTOT / BM, 3);   // (8, 32, 3)
    qkv_tf32_kernel<<<gqkv, 256, GEMM_SMEM>>>(x, Wq, Wk, Wv);

    attn_tf32_kernel<<<dim3(S_LEN / QROWS, NH, BATCH), 128, ATTN_SMEM>>>();

    dim3 gp(EMB / BN, MTOT / BM);        // (8, 32)
    gemm_tf32_kernel<<<gp, 256, GEMM_SMEM>>>(att, Wp, bp, out, MTOT, EMB, EMB);
}

// round 9
// speedup vs baseline: 1.1723x; 1.1723x over previous
#include <cuda_runtime.h>
#include <math.h>
#include <stdint.h>

#define S_LEN 2048
#define BATCH 2
#define EMB   1024
#define NH    16
#define HD    64
#define MTOT  (BATCH * S_LEN)   // 4096

__device__ float g_q[MTOT * EMB];
__device__ float g_k[MTOT * EMB];
__device__ float g_v[MTOT * EMB];
__device__ float g_att[MTOT * EMB];

__device__ __forceinline__ void mma_tf32(float c[4], uint32_t a0, uint32_t a1,
                                         uint32_t a2, uint32_t a3,
                                         uint32_t b0, uint32_t b1)
{
    asm volatile(
        "mma.sync.aligned.m16n8k8.row.col.f32.tf32.tf32.f32 "
        "{%0,%1,%2,%3}, {%4,%5,%6,%7}, {%8,%9}, {%0,%1,%2,%3};"
        : "+f"(c[0]), "+f"(c[1]), "+f"(c[2]), "+f"(c[3])
        : "r"(a0), "r"(a1), "r"(a2), "r"(a3), "r"(b0), "r"(b1));
}

__device__ __forceinline__ uint32_t tf32_rna(float x)
{
    uint32_t r;
    asm("cvt.rna.tf32.f32 %0, %1;" : "=r"(r) : "f"(x));
    return r;
}
__device__ __forceinline__ void split2(float x, float& hi, float& lo)
{
    hi = __uint_as_float(tf32_rna(x));
    lo = x - hi;
}
__device__ __forceinline__ uint32_t f2b(float x) { return __float_as_uint(x); }

__device__ __forceinline__ void cp16(void* smem, const void* gmem)
{
    uint32_t s = (uint32_t)__cvta_generic_to_shared(smem);
    asm volatile("cp.async.cg.shared.global [%0], [%1], 16;" :: "r"(s), "l"(gmem));
}
#define CP_COMMIT() asm volatile("cp.async.commit_group;" ::: "memory")
#define CP_WAIT1()  asm volatile("cp.async.wait_group 1;" ::: "memory")

// ---------------------------------------------------------------------------
// 3xTF32 GEMM (R7 structure, 512 threads): hi/lo pre-split smem, register
// gmem prefetch. 128x128x32 tile, 16 warps as 4(M) x 4(N), warp tile 32x32.
// ---------------------------------------------------------------------------
#define BM 128
#define BN 128
#define BK 32
#define ASTR 36
#define BSTR 136
#define GEMM_SMEM ((2 * BM * ASTR + 2 * BK * BSTR) * 4)   // 71680 B

__device__ __forceinline__ void gemm_tf32_body(
    const float* __restrict__ A, const float* __restrict__ B,
    const float* __restrict__ bias, float* __restrict__ C,
    int M, int N, int K)
{
    extern __shared__ float dsm[];
    float* Ah = dsm;                       // BM*ASTR
    float* Al = Ah + BM * ASTR;
    float* Bh = Al + BM * ASTR;            // BK*BSTR
    float* Bl = Bh + BK * BSTR;

    const int tid   = threadIdx.x;
    const int lane  = tid & 31;
    const int warp  = tid >> 5;            // 0..15
    const int warpM = warp >> 2;           // 0..3
    const int warpN = warp & 3;            // 0..3
    const int r     = lane >> 2;
    const int cq    = lane & 3;
    const int tm0   = blockIdx.y * BM;
    const int tn0   = blockIdx.x * BN;

    float acc[2][4][4];
    #pragma unroll
    for (int mt = 0; mt < 2; ++mt)
        #pragma unroll
        for (int nt = 0; nt < 4; ++nt)
            #pragma unroll
            for (int i = 0; i < 4; ++i) acc[mt][nt][i] = 0.f;

    const int arow = tid >> 3;            // 0..63
    const int acol = (tid & 7) * 4;       // 0..28
    const int brow = tid >> 6;            // 0..7
    const int bcol = (tid & 63) * 2;      // 0..126

    float4 a4[2];
    float2 b2[4];

    // Prologue: load tile 0
    #pragma unroll
    for (int i = 0; i < 2; ++i)
        a4[i] = *(const float4*)&A[(size_t)(tm0 + arow + i * 64) * K + acol];
    #pragma unroll
    for (int i = 0; i < 4; ++i)
        b2[i] = *(const float2*)&B[(size_t)(brow + i * 8) * N + tn0 + bcol];

    for (int k0 = 0; k0 < K; k0 += BK) {
        // Split + store current registers to smem (vectorized)
        #pragma unroll
        for (int i = 0; i < 2; ++i) {
            int row = arow + i * 64;
            float4 h, l;
            split2(a4[i].x, h.x, l.x); split2(a4[i].y, h.y, l.y);
            split2(a4[i].z, h.z, l.z); split2(a4[i].w, h.w, l.w);
            *(float4*)&Ah[row * ASTR + acol] = h;
            *(float4*)&Al[row * ASTR + acol] = l;
        }
        #pragma unroll
        for (int i = 0; i < 4; ++i) {
            int row = brow + i * 8;
            float2 h, l;
            split2(b2[i].x, h.x, l.x); split2(b2[i].y, h.y, l.y);
            *(float2*)&Bh[row * BSTR + bcol] = h;
            *(float2*)&Bl[row * BSTR + bcol] = l;
        }
        __syncthreads();

        // Prefetch next gmem tile into registers (overlaps with MMA below)
        int kn = k0 + BK;
        if (kn < K) {
            #pragma unroll
            for (int i = 0; i < 2; ++i)
                a4[i] = *(const float4*)&A[(size_t)(tm0 + arow + i * 64) * K + kn + acol];
            #pragma unroll
            for (int i = 0; i < 4; ++i)
                b2[i] = *(const float2*)&B[(size_t)(kn + brow + i * 8) * N + tn0 + bcol];
        }

        #pragma unroll
        for (int ks = 0; ks < 4; ++ks) {
            uint32_t ah[2][4], al[2][4];
            #pragma unroll
            for (int mt = 0; mt < 2; ++mt) {
                int row0 = warpM * 32 + mt * 16 + r;
                int kc   = ks * 8 + cq;
                ah[mt][0] = f2b(Ah[row0 * ASTR + kc]);
                ah[mt][1] = f2b(Ah[(row0 + 8) * ASTR + kc]);
                ah[mt][2] = f2b(Ah[row0 * ASTR + kc + 4]);
                ah[mt][3] = f2b(Ah[(row0 + 8) * ASTR + kc + 4]);
                al[mt][0] = f2b(Al[row0 * ASTR + kc]);
                al[mt][1] = f2b(Al[(row0 + 8) * ASTR + kc]);
                al[mt][2] = f2b(Al[row0 * ASTR + kc + 4]);
                al[mt][3] = f2b(Al[(row0 + 8) * ASTR + kc + 4]);
            }
            #pragma unroll
            for (int nt = 0; nt < 4; ++nt) {
                int ncol = warpN * 32 + nt * 8 + r;
                uint32_t bh0 = f2b(Bh[(ks * 8 + cq) * BSTR + ncol]);
                uint32_t bh1 = f2b(Bh[(ks * 8 + cq + 4) * BSTR + ncol]);
                uint32_t bl0 = f2b(Bl[(ks * 8 + cq) * BSTR + ncol]);
                uint32_t bl1 = f2b(Bl[(ks * 8 + cq + 4) * BSTR + ncol]);
                #pragma unroll
                for (int mt = 0; mt < 2; ++mt) {
                    mma_tf32(acc[mt][nt], ah[mt][0], ah[mt][1], ah[mt][2], ah[mt][3], bl0, bl1);
                    mma_tf32(acc[mt][nt], al[mt][0], al[mt][1], al[mt][2], al[mt][3], bh0, bh1);
                    mma_tf32(acc[mt][nt], ah[mt][0], ah[mt][1], ah[mt][2], ah[mt][3], bh0, bh1);
                }
            }
        }
        __syncthreads();
    }

    #pragma unroll
    for (int mt = 0; mt < 2; ++mt) {
        int row = tm0 + warpM * 32 + mt * 16 + r;
        #pragma unroll
        for (int nt = 0; nt < 4; ++nt) {
            int col = tn0 + warpN * 32 + nt * 8 + 2 * cq;
            float b0 = 0.f, b1 = 0.f;
            if (bias) { b0 = bias[col]; b1 = bias[col + 1]; }
            float2 v0 = make_float2(acc[mt][nt][0] + b0, acc[mt][nt][1] + b1);
            float2 v1 = make_float2(acc[mt][nt][2] + b0, acc[mt][nt][3] + b1);
            *(float2*)&C[(size_t)row * N + col]       = v0;
            *(float2*)&C[(size_t)(row + 8) * N + col] = v1;
        }
    }
}

__global__ __launch_bounds__(512) void gemm_tf32_kernel(
    const float* __restrict__ A, const float* __restrict__ B,
    const float* __restrict__ bias, float* __restrict__ C,
    int M, int N, int K)
{
    gemm_tf32_body(A, B, bias, C, M, N, K);
}

__global__ __launch_bounds__(512) void qkv_tf32_kernel(
    const float* __restrict__ x,
    const float* __restrict__ Wq, const float* __restrict__ Wk,
    const float* __restrict__ Wv)
{
    const float* W;
    float* C;
    if (blockIdx.z == 0)      { W = Wq; C = g_q; }
    else if (blockIdx.z == 1) { W = Wk; C = g_k; }
    else                      { W = Wv; C = g_v; }
    gemm_tf32_body(x, W, nullptr, C, MTOT, EMB, EMB);
}

// ---------------------------------------------------------------------------
// 1xTF32 flash attention: 256 threads (8 warps), 128 queries per CTA.
// Warp w owns query rows [w*16, w*16+16) — identical per-warp math to R7.
// cp.async double-buffered 64-key K/V tiles.
// ---------------------------------------------------------------------------
#define KSTR 68
#define VSTR 72
#define KSZ (64 * KSTR)
#define VSZ (64 * VSTR)
#define QROWS 128
#define ATTN_SMEM ((2 * (KSZ + VSZ) + QROWS * KSTR) * 4)   // 106496 B

__global__ __launch_bounds__(256) void attn_tf32_kernel()
{
    extern __shared__ float sm[];
    float* Ks[2] = { sm,       sm + KSZ + VSZ };
    float* Vs[2] = { sm + KSZ, sm + 2 * KSZ + VSZ };
    float* QP    = sm + 2 * (KSZ + VSZ);   // [128][KSTR]: Q staging, then P

    const int tid  = threadIdx.x;
    const int lane = tid & 31;
    const int warp = tid >> 5;           // 0..7
    const int r    = lane >> 2;
    const int cq   = lane & 3;
    const int bq   = gridDim.x - 1 - blockIdx.x;  // heavy blocks first
    const int h    = blockIdx.y;
    const int b    = blockIdx.z;
    const int qbase = bq * QROWS;
    const int nkb   = 2 * bq + 2;

    const int lrow = tid >> 4;           // 0..15
    const int lcol = (tid & 15) * 4;     // 0..60

    // Issue K/V tile 0 loads
    #pragma unroll
    for (int i = 0; i < 4; ++i) {
        int row = lrow + i * 16;
        size_t g = ((size_t)(b * S_LEN + row)) * EMB + h * HD + lcol;
        cp16(&Ks[0][row * KSTR + lcol], &g_k[g]);
        cp16(&Vs[0][row * VSTR + lcol], &g_v[g]);
    }
    CP_COMMIT();

    // Stage 128 Q rows, build rna fragments (scaled by 1/8)
    #pragma unroll
    for (int i = 0; i < 8; ++i) {
        int row = lrow + i * 16;
        *(float4*)&QP[row * KSTR + lcol] =
            *(const float4*)&g_q[((size_t)(b * S_LEN + qbase + row)) * EMB + h * HD + lcol];
    }
    __syncthreads();

    uint32_t qf[8][4];
    {
        int row0 = warp * 16 + r;
        #pragma unroll
        for (int ks = 0; ks < 8; ++ks) {
            int kc = ks * 8 + cq;
            qf[ks][0] = tf32_rna(QP[row0 * KSTR + kc] * 0.125f);
            qf[ks][1] = tf32_rna(QP[(row0 + 8) * KSTR + kc] * 0.125f);
            qf[ks][2] = tf32_rna(QP[row0 * KSTR + kc + 4] * 0.125f);
            qf[ks][3] = tf32_rna(QP[(row0 + 8) * KSTR + kc + 4] * 0.125f);
        }
    }
    __syncthreads();   // QP now free for P

    float o[8][4];
    #pragma unroll
    for (int nt = 0; nt < 8; ++nt)
        #pragma unroll
        for (int i = 0; i < 4; ++i) o[nt][i] = 0.f;
    float m0 = -1e30f, m1 = -1e30f, l0 = 0.f, l1 = 0.f;

    const int qr0 = warp * 16 + r;       // local q row in [0,128)
    const int qr1 = qr0 + 8;
    const int qg0 = qbase + qr0;         // global q row
    const int qg1 = qbase + qr1;

    for (int kb = 0; kb < nkb; ++kb) {
        const int cur = kb & 1;
        if (kb + 1 < nkb) {
            float* Kn = Ks[cur ^ 1];
            float* Vn = Vs[cur ^ 1];
            #pragma unroll
            for (int i = 0; i < 4; ++i) {
                int row = lrow + i * 16;
                size_t g = ((size_t)(b * S_LEN + (kb + 1) * 64 + row)) * EMB + h * HD + lcol;
                cp16(&Kn[row * KSTR + lcol], &g_k[g]);
                cp16(&Vn[row * VSTR + lcol], &g_v[g]);
            }
        }
        CP_COMMIT();
        CP_WAIT1();
        __syncthreads();

        const float* Kc = Ks[cur];
        const float* Vc = Vs[cur];

        // S = (Q/8) @ K^T  (1xTF32, rna)
        float s[8][4];
        #pragma unroll
        for (int nt = 0; nt < 8; ++nt)
            #pragma unroll
            for (int i = 0; i < 4; ++i) s[nt][i] = 0.f;
        #pragma unroll
        for (int ks = 0; ks < 8; ++ks) {
            int kc = ks * 8 + cq;
            #pragma unroll
            for (int nt = 0; nt < 8; ++nt) {
                int krow = nt * 8 + r;
                uint32_t b0 = tf32_rna(Kc[krow * KSTR + kc]);
                uint32_t b1 = tf32_rna(Kc[krow * KSTR + kc + 4]);
                mma_tf32(s[nt], qf[ks][0], qf[ks][1], qf[ks][2], qf[ks][3], b0, b1);
            }
        }

        // Causal mask (only the last two key tiles can clip any row)
        if (kb * 64 + 63 > qbase) {
            int kg0 = kb * 64;
            #pragma unroll
            for (int nt = 0; nt < 8; ++nt) {
                int kg = kg0 + nt * 8 + 2 * cq;
                if (kg     > qg0) s[nt][0] = -1e30f;
                if (kg + 1 > qg0) s[nt][1] = -1e30f;
                if (kg     > qg1) s[nt][2] = -1e30f;
                if (kg + 1 > qg1) s[nt][3] = -1e30f;
            }
        }

        float mx0 = -1e30f, mx1 = -1e30f;
        #pragma unroll
        for (int nt = 0; nt < 8; ++nt) {
            mx0 = fmaxf(mx0, fmaxf(s[nt][0], s[nt][1]));
            mx1 = fmaxf(mx1, fmaxf(s[nt][2], s[nt][3]));
        }
        mx0 = fmaxf(mx0, __shfl_xor_sync(0xffffffffu, mx0, 1));
        mx0 = fmaxf(mx0, __shfl_xor_sync(0xffffffffu, mx0, 2));
        mx1 = fmaxf(mx1, __shfl_xor_sync(0xffffffffu, mx1, 1));
        mx1 = fmaxf(mx1, __shfl_xor_sync(0xffffffffu, mx1, 2));
        float mn0 = fmaxf(m0, mx0), mn1 = fmaxf(m1, mx1);
        float sc0 = __expf(m0 - mn0), sc1 = __expf(m1 - mn1);
        m0 = mn0; m1 = mn1;
        float ls0 = 0.f, ls1 = 0.f;
        #pragma unroll
        for (int nt = 0; nt < 8; ++nt) {
            s[nt][0] = __expf(s[nt][0] - m0);
            s[nt][1] = __expf(s[nt][1] - m0);
            s[nt][2] = __expf(s[nt][2] - m1);
            s[nt][3] = __expf(s[nt][3] - m1);
            ls0 += s[nt][0] + s[nt][1];
            ls1 += s[nt][2] + s[nt][3];
        }
        ls0 += __shfl_xor_sync(0xffffffffu, ls0, 1);
        ls0 += __shfl_xor_sync(0xffffffffu, ls0, 2);
        ls1 += __shfl_xor_sync(0xffffffffu, ls1, 1);
        ls1 += __shfl_xor_sync(0xffffffffu, ls1, 2);
        l0 = l0 * sc0 + ls0;
        l1 = l1 * sc1 + ls1;
        #pragma unroll
        for (int nt = 0; nt < 8; ++nt) {
            o[nt][0] *= sc0; o[nt][1] *= sc0;
            o[nt][2] *= sc1; o[nt][3] *= sc1;
        }

        // P -> smem (rows warp*16..warp*16+15 are private to this warp)
        #pragma unroll
        for (int nt = 0; nt < 8; ++nt) {
            int kc = nt * 8 + 2 * cq;
            QP[qr0 * KSTR + kc]     = s[nt][0];
            QP[qr0 * KSTR + kc + 1] = s[nt][1];
            QP[qr1 * KSTR + kc]     = s[nt][2];
            QP[qr1 * KSTR + kc + 1] = s[nt][3];
        }
        __syncwarp();

        // O += P @ V  (1xTF32, rna)
        #pragma unroll
        for (int kv = 0; kv < 8; ++kv) {
            int kc = kv * 8 + cq;
            uint32_t p0 = tf32_rna(QP[qr0 * KSTR + kc]);
            uint32_t p1 = tf32_rna(QP[qr1 * KSTR + kc]);
            uint32_t p2 = tf32_rna(QP[qr0 * KSTR + kc + 4]);
            uint32_t p3 = tf32_rna(QP[qr1 * KSTR + kc + 4]);
            #pragma unroll
            for (int nt = 0; nt < 8; ++nt) {
                int ncol = nt * 8 + r;
                uint32_t b0 = tf32_rna(Vc[(kv * 8 + cq) * VSTR + ncol]);
                uint32_t b1 = tf32_rna(Vc[(kv * 8 + cq + 4) * VSTR + ncol]);
                mma_tf32(o[nt], p0, p1, p2, p3, b0, b1);
            }
        }
        __syncthreads();
    }

    float inv0 = 1.f / l0, inv1 = 1.f / l1;
    #pragma unroll
    for (int nt = 0; nt < 8; ++nt) {
        int col = h * HD + nt * 8 + 2 * cq;
        float2 v0 = make_float2(o[nt][0] * inv0, o[nt][1] * inv0);
        float2 v1 = make_float2(o[nt][2] * inv1, o[nt][3] * inv1);
        *(float2*)&g_att[((size_t)(b * S_LEN + qbase + qr0)) * EMB + col] = v0;
        *(float2*)&g_att[((size_t)(b * S_LEN + qbase + qr1)) * EMB + col] = v1;
    }
}

// ---------------------------------------------------------------------------
extern "C" void kernel_launch(void* const* d_in, const int* in_sizes, int n_in,
                              void* d_out, int out_size)
{
    const float* x  = (const float*)d_in[0];
    const float* Wq = (const float*)d_in[1];
    const float* Wk = (const float*)d_in[2];
    const float* Wv = (const float*)d_in[3];
    const float* Wp = (const float*)d_in[4];
    const float* bp = (const float*)d_in[5];
    float* out = (float*)d_out;

    float* att;
    cudaGetSymbolAddress((void**)&att, g_att);

    cudaFuncSetAttribute(qkv_tf32_kernel,  cudaFuncAttributeMaxDynamicSharedMemorySize, GEMM_SMEM);
    cudaFuncSetAttribute(gemm_tf32_kernel, cudaFuncAttributeMaxDynamicSharedMemorySize, GEMM_SMEM);
    cudaFuncSetAttribute(attn_tf32_kernel, cudaFuncAttributeMaxDynamicSharedMemorySize, ATTN_SMEM);

    dim3 gqkv(EMB / BN, MTOT / BM, 3);   // (8, 32, 3)
    qkv_tf32_kernel<<<gqkv, 512, GEMM_SMEM>>>(x, Wq, Wk, Wv);

    attn_tf32_kernel<<<dim3(S_LEN / QROWS, NH, BATCH), 256, ATTN_SMEM>>>();

    dim3 gp(EMB / BN, MTOT / BM);        // (8, 32)
    gemm_tf32_kernel<<<gp, 512, GEMM_SMEM>>>(att, Wp, bp, out, MTOT, EMB, EMB);
}

// round 10
// speedup vs baseline: 1.5896x; 1.3560x over previous
#include <cuda_runtime.h>
#include <cuda_bf16.h>
#include <math.h>
#include <stdint.h>

#define S_LEN 2048
#define BATCH 2
#define EMB   1024
#define NH    16
#define HD    64
#define MTOT  (BATCH * S_LEN)   // 4096

__device__ float g_q[MTOT * EMB];
__device__ float g_k[MTOT * EMB];
__device__ float g_v[MTOT * EMB];
__device__ float g_att[MTOT * EMB];

// ---- mma helpers ----------------------------------------------------------
__device__ __forceinline__ void mma_bf16(float c[4], uint32_t a0, uint32_t a1,
                                         uint32_t a2, uint32_t a3,
                                         uint32_t b0, uint32_t b1)
{
    asm volatile(
        "mma.sync.aligned.m16n8k16.row.col.f32.bf16.bf16.f32 "
        "{%0,%1,%2,%3}, {%4,%5,%6,%7}, {%8,%9}, {%0,%1,%2,%3};"
        : "+f"(c[0]), "+f"(c[1]), "+f"(c[2]), "+f"(c[3])
        : "r"(a0), "r"(a1), "r"(a2), "r"(a3), "r"(b0), "r"(b1));
}

__device__ __forceinline__ void mma_tf32(float c[4], uint32_t a0, uint32_t a1,
                                         uint32_t a2, uint32_t a3,
                                         uint32_t b0, uint32_t b1)
{
    asm volatile(
        "mma.sync.aligned.m16n8k8.row.col.f32.tf32.tf32.f32 "
        "{%0,%1,%2,%3}, {%4,%5,%6,%7}, {%8,%9}, {%0,%1,%2,%3};"
        : "+f"(c[0]), "+f"(c[1]), "+f"(c[2]), "+f"(c[3])
        : "r"(a0), "r"(a1), "r"(a2), "r"(a3), "r"(b0), "r"(b1));
}

__device__ __forceinline__ uint32_t tf32_rna(float x)
{
    uint32_t r;
    asm("cvt.rna.tf32.f32 %0, %1;" : "=r"(r) : "f"(x));
    return r;
}

// Pack two floats to bf16x2 (rn), return residuals.
__device__ __forceinline__ uint32_t pack_hi2(float a, float b, float& ra, float& rb)
{
    __nv_bfloat162 h = __floats2bfloat162_rn(a, b);   // x=a, y=b
    ra = a - __bfloat162float(h.x);
    rb = b - __bfloat162float(h.y);
    uint32_t u; memcpy(&u, &h, 4); return u;
}
__device__ __forceinline__ uint32_t pack_lo2(float ra, float rb)
{
    __nv_bfloat162 l = __floats2bfloat162_rn(ra, rb);
    uint32_t u; memcpy(&u, &l, 4); return u;
}

__device__ __forceinline__ void cp16(void* smem, const void* gmem)
{
    uint32_t s = (uint32_t)__cvta_generic_to_shared(smem);
    asm volatile("cp.async.cg.shared.global [%0], [%1], 16;" :: "r"(s), "l"(gmem));
}
#define CP_COMMIT() asm volatile("cp.async.commit_group;" ::: "memory")
#define CP_WAIT1()  asm volatile("cp.async.wait_group 1;" ::: "memory")

// ---------------------------------------------------------------------------
// 3xBF16 GEMM: C = A@B (+bias). 128x128x32 tile, 512 threads (16 warps 4x4),
// warp tile 32x32. Smem holds k-pair-packed bf16x2 hi/lo in fragment-friendly
// [pair][row/n] layout, stride 136 (== 8 mod 32 -> conflict-free frag loads).
// ---------------------------------------------------------------------------
#define BM 128
#define BN 128
#define BK 32
#define NPAIR 16            // BK/2 k-pairs
#define PSTR 136            // uint32 stride per pair row
#define GEMM_SMEM (4 * NPAIR * PSTR * 4)   // Ah,Al,Bh,Bl = 34816 B

__device__ __forceinline__ void gemm_bf16_body(
    const float* __restrict__ A, const float* __restrict__ B,
    const float* __restrict__ bias, float* __restrict__ C,
    int M, int N, int K)
{
    extern __shared__ uint32_t usm[];
    uint32_t* Ahp = usm;                     // [NPAIR][PSTR] rows 0..127
    uint32_t* Alp = Ahp + NPAIR * PSTR;
    uint32_t* Bhp = Alp + NPAIR * PSTR;      // [NPAIR][PSTR] cols 0..127
    uint32_t* Blp = Bhp + NPAIR * PSTR;

    const int tid   = threadIdx.x;
    const int lane  = tid & 31;
    const int warp  = tid >> 5;            // 0..15
    const int warpM = warp >> 2;           // 0..3
    const int warpN = warp & 3;            // 0..3
    const int r     = lane >> 2;           // 0..7
    const int cq    = lane & 3;            // 0..3
    const int tm0   = blockIdx.y * BM;
    const int tn0   = blockIdx.x * BN;

    float acc[2][4][4];
    #pragma unroll
    for (int mt = 0; mt < 2; ++mt)
        #pragma unroll
        for (int nt = 0; nt < 4; ++nt)
            #pragma unroll
            for (int i = 0; i < 4; ++i) acc[mt][nt][i] = 0.f;

    const int arow  = tid >> 3;            // 0..63
    const int acol  = (tid & 7) * 4;       // 0..28 (4 consecutive k)
    const int p0a   = acol >> 1;           // first k-pair for this thread
    const int brow2 = (tid >> 6) * 2;      // 0,2,..,14 (k within 16-row pass)
    const int bcol  = (tid & 63) * 2;      // 0..126 (2 consecutive n)

    float4 a4[2];
    float2 bk0[2], bk1[2];                 // per pass: rows kb, kb+1

    // Prologue: load k-tile 0
    #pragma unroll
    for (int i = 0; i < 2; ++i)
        a4[i] = *(const float4*)&A[(size_t)(tm0 + arow + i * 64) * K + acol];
    #pragma unroll
    for (int p = 0; p < 2; ++p) {
        int kb = p * 16 + brow2;
        bk0[p] = *(const float2*)&B[(size_t)kb * N + tn0 + bcol];
        bk1[p] = *(const float2*)&B[(size_t)(kb + 1) * N + tn0 + bcol];
    }

    for (int k0 = 0; k0 < K; k0 += BK) {
        // ---- split + pack + store to smem ----
        #pragma unroll
        for (int i = 0; i < 2; ++i) {
            int row = arow + i * 64;
            float rx, ry, rz, rw;
            uint32_t h01 = pack_hi2(a4[i].x, a4[i].y, rx, ry);
            uint32_t h23 = pack_hi2(a4[i].z, a4[i].w, rz, rw);
            Ahp[p0a * PSTR + row]       = h01;
            Ahp[(p0a + 1) * PSTR + row] = h23;
            Alp[p0a * PSTR + row]       = pack_lo2(rx, ry);
            Alp[(p0a + 1) * PSTR + row] = pack_lo2(rz, rw);
        }
        #pragma unroll
        for (int p = 0; p < 2; ++p) {
            int pi = p * 8 + (brow2 >> 1);   // k-pair index
            float r00, r10, r01, r11;
            uint32_t h_n0 = pack_hi2(bk0[p].x, bk1[p].x, r00, r10);  // {B[k][n], B[k+1][n]}
            uint32_t h_n1 = pack_hi2(bk0[p].y, bk1[p].y, r01, r11);
            Bhp[pi * PSTR + bcol]     = h_n0;
            Bhp[pi * PSTR + bcol + 1] = h_n1;
            Blp[pi * PSTR + bcol]     = pack_lo2(r00, r10);
            Blp[pi * PSTR + bcol + 1] = pack_lo2(r01, r11);
        }
        __syncthreads();

        // ---- prefetch next gmem tile (overlaps MMA) ----
        int kn = k0 + BK;
        if (kn < K) {
            #pragma unroll
            for (int i = 0; i < 2; ++i)
                a4[i] = *(const float4*)&A[(size_t)(tm0 + arow + i * 64) * K + kn + acol];
            #pragma unroll
            for (int p = 0; p < 2; ++p) {
                int kb = kn + p * 16 + brow2;
                bk0[p] = *(const float2*)&B[(size_t)kb * N + tn0 + bcol];
                bk1[p] = *(const float2*)&B[(size_t)(kb + 1) * N + tn0 + bcol];
            }
        }

        // ---- MMA: 2 ks-steps of K=16 ----
        #pragma unroll
        for (int ks = 0; ks < 2; ++ks) {
            uint32_t ah[2][4], al[2][4];
            #pragma unroll
            for (int mt = 0; mt < 2; ++mt) {
                int row0 = warpM * 32 + mt * 16 + r;
                int pa   = ks * 8 + cq;
                ah[mt][0] = Ahp[pa * PSTR + row0];
                ah[mt][1] = Ahp[pa * PSTR + row0 + 8];
                ah[mt][2] = Ahp[(pa + 4) * PSTR + row0];
                ah[mt][3] = Ahp[(pa + 4) * PSTR + row0 + 8];
                al[mt][0] = Alp[pa * PSTR + row0];
                al[mt][1] = Alp[pa * PSTR + row0 + 8];
                al[mt][2] = Alp[(pa + 4) * PSTR + row0];
                al[mt][3] = Alp[(pa + 4) * PSTR + row0 + 8];
            }
            #pragma unroll
            for (int nt = 0; nt < 4; ++nt) {
                int ncol = warpN * 32 + nt * 8 + r;
                uint32_t bh0 = Bhp[(ks * 8 + cq) * PSTR + ncol];
                uint32_t bh1 = Bhp[(ks * 8 + cq + 4) * PSTR + ncol];
                uint32_t bl0 = Blp[(ks * 8 + cq) * PSTR + ncol];
                uint32_t bl1 = Blp[(ks * 8 + cq + 4) * PSTR + ncol];
                #pragma unroll
                for (int mt = 0; mt < 2; ++mt) {
                    mma_bf16(acc[mt][nt], ah[mt][0], ah[mt][1], ah[mt][2], ah[mt][3], bl0, bl1);
                    mma_bf16(acc[mt][nt], al[mt][0], al[mt][1], al[mt][2], al[mt][3], bh0, bh1);
                    mma_bf16(acc[mt][nt], ah[mt][0], ah[mt][1], ah[mt][2], ah[mt][3], bh0, bh1);
                }
            }
        }
        __syncthreads();
    }

    #pragma unroll
    for (int mt = 0; mt < 2; ++mt) {
        int row = tm0 + warpM * 32 + mt * 16 + r;
        #pragma unroll
        for (int nt = 0; nt < 4; ++nt) {
            int col = tn0 + warpN * 32 + nt * 8 + 2 * cq;
            float b0 = 0.f, b1 = 0.f;
            if (bias) { b0 = bias[col]; b1 = bias[col + 1]; }
            float2 v0 = make_float2(acc[mt][nt][0] + b0, acc[mt][nt][1] + b1);
            float2 v1 = make_float2(acc[mt][nt][2] + b0, acc[mt][nt][3] + b1);
            *(float2*)&C[(size_t)row * N + col]       = v0;
            *(float2*)&C[(size_t)(row + 8) * N + col] = v1;
        }
    }
}

__global__ __launch_bounds__(512) void gemm_bf16_kernel(
    const float* __restrict__ A, const float* __restrict__ B,
    const float* __restrict__ bias, float* __restrict__ C,
    int M, int N, int K)
{
    gemm_bf16_body(A, B, bias, C, M, N, K);
}

__global__ __launch_bounds__(512) void qkv_bf16_kernel(
    const float* __restrict__ x,
    const float* __restrict__ Wq, const float* __restrict__ Wk,
    const float* __restrict__ Wv)
{
    const float* W;
    float* C;
    if (blockIdx.z == 0)      { W = Wq; C = g_q; }
    else if (blockIdx.z == 1) { W = Wk; C = g_k; }
    else                      { W = Wv; C = g_v; }
    gemm_bf16_body(x, W, nullptr, C, MTOT, EMB, EMB);
}

// ---------------------------------------------------------------------------
// 1xTF32 flash attention (R7 version, best measured): 128 threads, 64 q/CTA,
// cp.async double-buffered 64-key K/V tiles.
// ---------------------------------------------------------------------------
#define KSTR 68
#define VSTR 72
#define KSZ (64 * KSTR)
#define VSZ (64 * VSTR)
#define ATTN_SMEM ((2 * (KSZ + VSZ) + KSZ) * 4)   // 89088 B

__global__ __launch_bounds__(128) void attn_tf32_kernel()
{
    extern __shared__ float sm[];
    float* Ks[2] = { sm,            sm + KSZ + VSZ };
    float* Vs[2] = { sm + KSZ,      sm + 2 * KSZ + VSZ };
    float* QP    = sm + 2 * (KSZ + VSZ);

    const int tid  = threadIdx.x;
    const int lane = tid & 31;
    const int warp = tid >> 5;
    const int r    = lane >> 2;
    const int cq   = lane & 3;
    const int bq   = gridDim.x - 1 - blockIdx.x;
    const int h    = blockIdx.y;
    const int b    = blockIdx.z;
    const int qbase = bq * 64;

    const int lrow = tid >> 4;           // 0..7
    const int lcol = (tid & 15) * 4;     // 0..60

    // Issue tile 0 K/V loads immediately
    {
        #pragma unroll
        for (int i = 0; i < 8; ++i) {
            int row = lrow + i * 8;
            size_t g = ((size_t)(b * S_LEN + row)) * EMB + h * HD + lcol;
            cp16(&Ks[0][row * KSTR + lcol], &g_k[g]);
            cp16(&Vs[0][row * VSTR + lcol], &g_v[g]);
        }
        CP_COMMIT();
    }

    // Stage Q, build rna-rounded fragments (scaled by 1/8)
    #pragma unroll
    for (int i = 0; i < 8; ++i) {
        int row = lrow + i * 8;
        *(float4*)&QP[row * KSTR + lcol] =
            *(const float4*)&g_q[((size_t)(b * S_LEN + qbase + row)) * EMB + h * HD + lcol];
    }
    __syncthreads();

    uint32_t qf[8][4];
    {
        int row0 = warp * 16 + r;
        #pragma unroll
        for (int ks = 0; ks < 8; ++ks) {
            int kc = ks * 8 + cq;
            qf[ks][0] = tf32_rna(QP[row0 * KSTR + kc] * 0.125f);
            qf[ks][1] = tf32_rna(QP[(row0 + 8) * KSTR + kc] * 0.125f);
            qf[ks][2] = tf32_rna(QP[row0 * KSTR + kc + 4] * 0.125f);
            qf[ks][3] = tf32_rna(QP[(row0 + 8) * KSTR + kc + 4] * 0.125f);
        }
    }
    __syncthreads();   // QP now free for P

    float o[8][4];
    #pragma unroll
    for (int nt = 0; nt < 8; ++nt)
        #pragma unroll
        for (int i = 0; i < 4; ++i) o[nt][i] = 0.f;
    float m0 = -1e30f, m1 = -1e30f, l0 = 0.f, l1 = 0.f;

    const int qr0 = warp * 16 + r;
    const int qr1 = qr0 + 8;

    for (int kb = 0; kb <= bq; ++kb) {
        const int cur = kb & 1;
        if (kb < bq) {
            float* Kn = Ks[cur ^ 1];
            float* Vn = Vs[cur ^ 1];
            #pragma unroll
            for (int i = 0; i < 8; ++i) {
                int row = lrow + i * 8;
                size_t g = ((size_t)(b * S_LEN + (kb + 1) * 64 + row)) * EMB + h * HD + lcol;
                cp16(&Kn[row * KSTR + lcol], &g_k[g]);
                cp16(&Vn[row * VSTR + lcol], &g_v[g]);
            }
        }
        CP_COMMIT();
        CP_WAIT1();
        __syncthreads();

        const float* Kc = Ks[cur];
        const float* Vc = Vs[cur];

        float s[8][4];
        #pragma unroll
        for (int nt = 0; nt < 8; ++nt)
            #pragma unroll
            for (int i = 0; i < 4; ++i) s[nt][i] = 0.f;
        #pragma unroll
        for (int ks = 0; ks < 8; ++ks) {
            int kc = ks * 8 + cq;
            #pragma unroll
            for (int nt = 0; nt < 8; ++nt) {
                int krow = nt * 8 + r;
                uint32_t b0 = tf32_rna(Kc[krow * KSTR + kc]);
                uint32_t b1 = tf32_rna(Kc[krow * KSTR + kc + 4]);
                mma_tf32(s[nt], qf[ks][0], qf[ks][1], qf[ks][2], qf[ks][3], b0, b1);
            }
        }

        if (kb == bq) {
            #pragma unroll
            for (int nt = 0; nt < 8; ++nt) {
                int kc = nt * 8 + 2 * cq;
                if (kc     > qr0) s[nt][0] = -1e30f;
                if (kc + 1 > qr0) s[nt][1] = -1e30f;
                if (kc     > qr1) s[nt][2] = -1e30f;
                if (kc + 1 > qr1) s[nt][3] = -1e30f;
            }
        }

        float mx0 = -1e30f, mx1 = -1e30f;
        #pragma unroll
        for (int nt = 0; nt < 8; ++nt) {
            mx0 = fmaxf(mx0, fmaxf(s[nt][0], s[nt][1]));
            mx1 = fmaxf(mx1, fmaxf(s[nt][2], s[nt][3]));
        }
        mx0 = fmaxf(mx0, __shfl_xor_sync(0xffffffffu, mx0, 1));
        mx0 = fmaxf(mx0, __shfl_xor_sync(0xffffffffu, mx0, 2));
        mx1 = fmaxf(mx1, __shfl_xor_sync(0xffffffffu, mx1, 1));
        mx1 = fmaxf(mx1, __shfl_xor_sync(0xffffffffu, mx1, 2));
        float mn0 = fmaxf(m0, mx0), mn1 = fmaxf(m1, mx1);
        float sc0 = __expf(m0 - mn0), sc1 = __expf(m1 - mn1);
        m0 = mn0; m1 = mn1;
        float ls0 = 0.f, ls1 = 0.f;
        #pragma unroll
        for (int nt = 0; nt < 8; ++nt) {
            s[nt][0] = __expf(s[nt][0] - m0);
            s[nt][1] = __expf(s[nt][1] - m0);
            s[nt][2] = __expf(s[nt][2] - m1);
            s[nt][3] = __expf(s[nt][3] - m1);
            ls0 += s[nt][0] + s[nt][1];
            ls1 += s[nt][2] + s[nt][3];
        }
        ls0 += __shfl_xor_sync(0xffffffffu, ls0, 1);
        ls0 += __shfl_xor_sync(0xffffffffu, ls0, 2);
        ls1 += __shfl_xor_sync(0xffffffffu, ls1, 1);
        ls1 += __shfl_xor_sync(0xffffffffu, ls1, 2);
        l0 = l0 * sc0 + ls0;
        l1 = l1 * sc1 + ls1;
        #pragma unroll
        for (int nt = 0; nt < 8; ++nt) {
            o[nt][0] *= sc0; o[nt][1] *= sc0;
            o[nt][2] *= sc1; o[nt][3] *= sc1;
        }

        #pragma unroll
        for (int nt = 0; nt < 8; ++nt) {
            int kc = nt * 8 + 2 * cq;
            QP[qr0 * KSTR + kc]     = s[nt][0];
            QP[qr0 * KSTR + kc + 1] = s[nt][1];
            QP[qr1 * KSTR + kc]     = s[nt][2];
            QP[qr1 * KSTR + kc + 1] = s[nt][3];
        }
        __syncwarp();

        #pragma unroll
        for (int kv = 0; kv < 8; ++kv) {
            int kc = kv * 8 + cq;
            uint32_t p0 = tf32_rna(QP[qr0 * KSTR + kc]);
            uint32_t p1 = tf32_rna(QP[qr1 * KSTR + kc]);
            uint32_t p2 = tf32_rna(QP[qr0 * KSTR + kc + 4]);
            uint32_t p3 = tf32_rna(QP[qr1 * KSTR + kc + 4]);
            #pragma unroll
            for (int nt = 0; nt < 8; ++nt) {
                int ncol = nt * 8 + r;
                uint32_t b0 = tf32_rna(Vc[(kv * 8 + cq) * VSTR + ncol]);
                uint32_t b1 = tf32_rna(Vc[(kv * 8 + cq + 4) * VSTR + ncol]);
                mma_tf32(o[nt], p0, p1, p2, p3, b0, b1);
            }
        }
        __syncthreads();
    }

    float inv0 = 1.f / l0, inv1 = 1.f / l1;
    #pragma unroll
    for (int nt = 0; nt < 8; ++nt) {
        int col = h * HD + nt * 8 + 2 * cq;
        float2 v0 = make_float2(o[nt][0] * inv0, o[nt][1] * inv0);
        float2 v1 = make_float2(o[nt][2] * inv1, o[nt][3] * inv1);
        *(float2*)&g_att[((size_t)(b * S_LEN + qbase + qr0)) * EMB + col] = v0;
        *(float2*)&g_att[((size_t)(b * S_LEN + qbase + qr1)) * EMB + col] = v1;
    }
}

// ---------------------------------------------------------------------------
extern "C" void kernel_launch(void* const* d_in, const int* in_sizes, int n_in,
                              void* d_out, int out_size)
{
    const float* x  = (const float*)d_in[0];
    const float* Wq = (const float*)d_in[1];
    const float* Wk = (const float*)d_in[2];
    const float* Wv = (const float*)d_in[3];
    const float* Wp = (const float*)d_in[4];
    const float* bp = (const float*)d_in[5];
    float* out = (float*)d_out;

    float* att;
    cudaGetSymbolAddress((void**)&att, g_att);

    cudaFuncSetAttribute(qkv_bf16_kernel,  cudaFuncAttributeMaxDynamicSharedMemorySize, GEMM_SMEM);
    cudaFuncSetAttribute(gemm_bf16_kernel, cudaFuncAttributeMaxDynamicSharedMemorySize, GEMM_SMEM);
    cudaFuncSetAttribute(attn_tf32_kernel, cudaFuncAttributeMaxDynamicSharedMemorySize, ATTN_SMEM);

    dim3 gqkv(EMB / BN, MTOT / BM, 3);   // (8, 32, 3)
    qkv_bf16_kernel<<<gqkv, 512, GEMM_SMEM>>>(x, Wq, Wk, Wv);

    attn_tf32_kernel<<<dim3(S_LEN / 64, NH, BATCH), 128, ATTN_SMEM>>>();

    dim3 gp(EMB / BN, MTOT / BM);        // (8, 32)
    gemm_bf16_kernel<<<gp, 512, GEMM_SMEM>>>(att, Wp, bp, out, MTOT, EMB, EMB);
}

// round 13
// speedup vs baseline: 1.7696x; 1.1132x over previous
#include <cuda_runtime.h>
#include <cuda_bf16.h>
#include <math.h>
#include <stdint.h>
#include <string.h>

#define S_LEN 2048
#define BATCH 2
#define EMB   1024
#define NH    16
#define HD    64
#define MTOT  (BATCH * S_LEN)   // 4096

// fp32 intermediates
__device__ float g_q[MTOT * EMB];
__device__ float g_k[MTOT * EMB];
__device__ float g_v[MTOT * EMB];
__device__ float g_att[MTOT * EMB];

// Pre-split tiled bf16x2 buffers.
// A-operand layout: tile (mb,kt) at offset (mb*32+kt)*2176; in-tile idx = pa*136 + row.
// B-operand layout: tile (nb,kt) at offset (nb*32+kt)*2176; in-tile idx = pi*136 + n.
#define TILE_U32 2176                       // 16 pairs * 136
#define ATILES_U32 (32 * 32 * TILE_U32)     // 4096 rows x 1024 k
#define BTILES_U32 (8 * 32 * TILE_U32)      // 1024 k x 1024 n
__device__ uint32_t g_xh[ATILES_U32],  g_xl[ATILES_U32];
__device__ uint32_t g_ath[ATILES_U32], g_atl[ATILES_U32];
__device__ uint32_t g_wh[4][BTILES_U32], g_wl[4][BTILES_U32];   // q,k,v,p

// ---- helpers --------------------------------------------------------------
__device__ __forceinline__ void mma_bf16(float c[4], uint32_t a0, uint32_t a1,
                                         uint32_t a2, uint32_t a3,
                                         uint32_t b0, uint32_t b1)
{
    asm volatile(
        "mma.sync.aligned.m16n8k16.row.col.f32.bf16.bf16.f32 "
        "{%0,%1,%2,%3}, {%4,%5,%6,%7}, {%8,%9}, {%0,%1,%2,%3};"
        : "+f"(c[0]), "+f"(c[1]), "+f"(c[2]), "+f"(c[3])
        : "r"(a0), "r"(a1), "r"(a2), "r"(a3), "r"(b0), "r"(b1));
}
__device__ __forceinline__ void mma_tf32(float c[4], uint32_t a0, uint32_t a1,
                                         uint32_t a2, uint32_t a3,
                                         uint32_t b0, uint32_t b1)
{
    asm volatile(
        "mma.sync.aligned.m16n8k8.row.col.f32.tf32.tf32.f32 "
        "{%0,%1,%2,%3}, {%4,%5,%6,%7}, {%8,%9}, {%0,%1,%2,%3};"
        : "+f"(c[0]), "+f"(c[1]), "+f"(c[2]), "+f"(c[3])
        : "r"(a0), "r"(a1), "r"(a2), "r"(a3), "r"(b0), "r"(b1));
}
__device__ __forceinline__ uint32_t tf32_rna(float x)
{
    uint32_t r;
    asm("cvt.rna.tf32.f32 %0, %1;" : "=r"(r) : "f"(x));
    return r;
}
__device__ __forceinline__ uint32_t pack_hi2(float a, float b, float& ra, float& rb)
{
    __nv_bfloat162 h = __floats2bfloat162_rn(a, b);
    ra = a - __bfloat162float(h.x);
    rb = b - __bfloat162float(h.y);
    uint32_t u; memcpy(&u, &h, 4); return u;
}
__device__ __forceinline__ uint32_t pack_lo2(float ra, float rb)
{
    __nv_bfloat162 l = __floats2bfloat162_rn(ra, rb);
    uint32_t u; memcpy(&u, &l, 4); return u;
}
__device__ __forceinline__ void cp16(void* smem, const void* gmem)
{
    uint32_t s = (uint32_t)__cvta_generic_to_shared(smem);
    asm volatile("cp.async.cg.shared.global [%0], [%1], 16;" :: "r"(s), "l"(gmem));
}
#define CP_COMMIT() asm volatile("cp.async.commit_group;" ::: "memory")
#define CP_WAIT0()  asm volatile("cp.async.wait_group 0;" ::: "memory")
#define CP_WAIT1()  asm volatile("cp.async.wait_group 1;" ::: "memory")

// ---------------------------------------------------------------------------
// Split kernels: fp32 -> tiled pair-packed bf16x2 hi/lo.
// ---------------------------------------------------------------------------
// A-operand (row-major [4096][1024]). grid (32 kt, 32 mb), 256 threads.
__global__ __launch_bounds__(256) void split_a_kernel(
    const float* __restrict__ src, uint32_t* __restrict__ dh, uint32_t* __restrict__ dl)
{
    __shared__ float s[128 * 33];
    const int kt = blockIdx.x, mb = blockIdx.y;
    const int t = threadIdx.x;
    {
        int row = t >> 1, half = (t & 1) * 16;
        const float* sp = src + (size_t)(mb * 128 + row) * EMB + kt * 32 + half;
        #pragma unroll
        for (int j = 0; j < 4; ++j) {
            float4 v = *(const float4*)(sp + j * 4);
            s[row * 33 + half + j * 4 + 0] = v.x;
            s[row * 33 + half + j * 4 + 1] = v.y;
            s[row * 33 + half + j * 4 + 2] = v.z;
            s[row * 33 + half + j * 4 + 3] = v.w;
        }
    }
    __syncthreads();
    size_t off = (size_t)(mb * 32 + kt) * TILE_U32;
    for (int idx = t; idx < TILE_U32; idx += 256) {
        int pa = idx / 136, rw = idx - pa * 136;
        uint32_t h = 0, l = 0;
        if (rw < 128) {
            float a = s[rw * 33 + 2 * pa], b = s[rw * 33 + 2 * pa + 1];
            float ra, rb;
            h = pack_hi2(a, b, ra, rb);
            l = pack_lo2(ra, rb);
        }
        dh[off + idx] = h;
        dl[off + idx] = l;
    }
}

// B-operand (weights, row-major [1024 k][1024 n]). grid (32 kt, 8 nb, 4 z), 256 thr.
__global__ __launch_bounds__(256) void split_w_kernel(
    const float* __restrict__ Wq, const float* __restrict__ Wk,
    const float* __restrict__ Wv, const float* __restrict__ Wp)
{
    __shared__ float s[32 * 129];
    const int kt = blockIdx.x, nb = blockIdx.y, z = blockIdx.z;
    const float* src = (z == 0) ? Wq : (z == 1) ? Wk : (z == 2) ? Wv : Wp;
    const int t = threadIdx.x;
    {
        int row = t >> 3, off8 = (t & 7) * 16;
        const float* sp = src + (size_t)(kt * 32 + row) * EMB + nb * 128 + off8;
        #pragma unroll
        for (int j = 0; j < 4; ++j) {
            float4 v = *(const float4*)(sp + j * 4);
            s[row * 129 + off8 + j * 4 + 0] = v.x;
            s[row * 129 + off8 + j * 4 + 1] = v.y;
            s[row * 129 + off8 + j * 4 + 2] = v.z;
            s[row * 129 + off8 + j * 4 + 3] = v.w;
        }
    }
    __syncthreads();
    size_t off = (size_t)(nb * 32 + kt) * TILE_U32;
    uint32_t* dh = g_wh[z];
    uint32_t* dl = g_wl[z];
    for (int idx = t; idx < TILE_U32; idx += 256) {
        int pi = idx / 136, n = idx - pi * 136;
        uint32_t h = 0, l = 0;
        if (n < 128) {
            float a = s[(2 * pi) * 129 + n], b = s[(2 * pi + 1) * 129 + n];
            float ra, rb;
            h = pack_hi2(a, b, ra, rb);
            l = pack_lo2(ra, rb);
        }
        dh[off + idx] = h;
        dl[off + idx] = l;
    }
}

// ---------------------------------------------------------------------------
// 3xBF16 GEMM from pre-split tiles, 3-stage cp.async pipeline.
// 128x128 output tile, 512 threads (16 warps 4x4), warp tile 32x32, 32 k-tiles.
// ---------------------------------------------------------------------------
#define STG_U32 (4 * TILE_U32)                 // Ah|Al|Bh|Bl per stage = 8704
#define GEMM_SMEM (3 * STG_U32 * 4)            // 104448 B
#define NKT 32

__device__ __forceinline__ void gemm3_body(
    const uint32_t* __restrict__ Ah, const uint32_t* __restrict__ Al,
    const uint32_t* __restrict__ Bh, const uint32_t* __restrict__ Bl,
    const float* __restrict__ bias, float* __restrict__ C)
{
    extern __shared__ uint32_t usm[];

    const int tid   = threadIdx.x;
    const int lane  = tid & 31;
    const int warp  = tid >> 5;
    const int warpM = warp >> 2;
    const int warpN = warp & 3;
    const int r     = lane >> 2;
    const int cq    = lane & 3;
    const int nb    = blockIdx.x;
    const int mb    = blockIdx.y;
    const size_t aBase = (size_t)mb * 32 * TILE_U32;
    const size_t bBase = (size_t)nb * 32 * TILE_U32;

    float acc[2][4][4];
    #pragma unroll
    for (int mt = 0; mt < 2; ++mt)
        #pragma unroll
        for (int nt = 0; nt < 4; ++nt)
            #pragma unroll
            for (int i = 0; i < 4; ++i) acc[mt][nt][i] = 0.f;

    #define ISSUE(kt_)                                                          \
    {                                                                           \
        uint32_t* dst = usm + ((kt_) % 3) * STG_U32;                            \
        const uint32_t* sah = Ah + aBase + (size_t)(kt_) * TILE_U32;            \
        const uint32_t* sal = Al + aBase + (size_t)(kt_) * TILE_U32;            \
        const uint32_t* sbh = Bh + bBase + (size_t)(kt_) * TILE_U32;            \
        const uint32_t* sbl = Bl + bBase + (size_t)(kt_) * TILE_U32;            \
        for (int c = tid; c < 544; c += 512) {                                  \
            cp16(dst + c * 4,                sah + c * 4);                      \
            cp16(dst + TILE_U32 + c * 4,     sal + c * 4);                      \
            cp16(dst + 2 * TILE_U32 + c * 4, sbh + c * 4);                      \
            cp16(dst + 3 * TILE_U32 + c * 4, sbl + c * 4);                      \
        }                                                                       \
    }

    ISSUE(0) CP_COMMIT();
    ISSUE(1) CP_COMMIT();

    for (int kt = 0; kt < NKT; ++kt) {
        if (kt + 2 < NKT) CP_WAIT1(); else CP_WAIT0();
        __syncthreads();
        if (kt + 2 < NKT) { ISSUE(kt + 2) CP_COMMIT(); }

        const uint32_t* Ahs = usm + (kt % 3) * STG_U32;
        const uint32_t* Als = Ahs + TILE_U32;
        const uint32_t* Bhs = Ahs + 2 * TILE_U32;
        const uint32_t* Bls = Ahs + 3 * TILE_U32;

        #pragma unroll
        for (int ks = 0; ks < 2; ++ks) {
            uint32_t ah[2][4], al[2][4];
            #pragma unroll
            for (int mt = 0; mt < 2; ++mt) {
                int row0 = warpM * 32 + mt * 16 + r;
                int pa   = ks * 8 + cq;
                ah[mt][0] = Ahs[pa * 136 + row0];
                ah[mt][1] = Ahs[pa * 136 + row0 + 8];
                ah[mt][2] = Ahs[(pa + 4) * 136 + row0];
                ah[mt][3] = Ahs[(pa + 4) * 136 + row0 + 8];
                al[mt][0] = Als[pa * 136 + row0];
                al[mt][1] = Als[pa * 136 + row0 + 8];
                al[mt][2] = Als[(pa + 4) * 136 + row0];
                al[mt][3] = Als[(pa + 4) * 136 + row0 + 8];
            }
            #pragma unroll
            for (int nt = 0; nt < 4; ++nt) {
                int ncol = warpN * 32 + nt * 8 + r;
                uint32_t bh0 = Bhs[(ks * 8 + cq) * 136 + ncol];
                uint32_t bh1 = Bhs[(ks * 8 + cq + 4) * 136 + ncol];
                uint32_t bl0 = Bls[(ks * 8 + cq) * 136 + ncol];
                uint32_t bl1 = Bls[(ks * 8 + cq + 4) * 136 + ncol];
                #pragma unroll
                for (int mt = 0; mt < 2; ++mt) {
                    mma_bf16(acc[mt][nt], ah[mt][0], ah[mt][1], ah[mt][2], ah[mt][3], bl0, bl1);
                    mma_bf16(acc[mt][nt], al[mt][0], al[mt][1], al[mt][2], al[mt][3], bh0, bh1);
                    mma_bf16(acc[mt][nt], ah[mt][0], ah[mt][1], ah[mt][2], ah[mt][3], bh0, bh1);
                }
            }
        }
    }
    #undef ISSUE

    #pragma unroll
    for (int mt = 0; mt < 2; ++mt) {
        int row = mb * 128 + warpM * 32 + mt * 16 + r;
        #pragma unroll
        for (int nt = 0; nt < 4; ++nt) {
            int col = nb * 128 + warpN * 32 + nt * 8 + 2 * cq;
            float b0 = 0.f, b1 = 0.f;
            if (bias) { b0 = bias[col]; b1 = bias[col + 1]; }
            float2 v0 = make_float2(acc[mt][nt][0] + b0, acc[mt][nt][1] + b1);
            float2 v1 = make_float2(acc[mt][nt][2] + b0, acc[mt][nt][3] + b1);
            *(float2*)&C[(size_t)row * EMB + col]       = v0;
            *(float2*)&C[(size_t)(row + 8) * EMB + col] = v1;
        }
    }
}

__global__ __launch_bounds__(512) void qkv_gemm_kernel()
{
    const int z = blockIdx.z;
    float* C = (z == 0) ? g_q : (z == 1) ? g_k : g_v;
    gemm3_body(g_xh, g_xl, g_wh[z], g_wl[z], nullptr, C);
}

__global__ __launch_bounds__(512) void proj_gemm_kernel(float* __restrict__ out,
                                                        const float* __restrict__ bias)
{
    gemm3_body(g_ath, g_atl, g_wh[3], g_wl[3], bias, out);
}

// ---------------------------------------------------------------------------
// 1xTF32 flash attention (unchanged from R10): 128 threads, 64 q/CTA,
// cp.async double-buffered 64-key K/V tiles.
// ---------------------------------------------------------------------------
#define KSTR 68
#define VSTR 72
#define KSZ (64 * KSTR)
#define VSZ (64 * VSTR)
#define ATTN_SMEM ((2 * (KSZ + VSZ) + KSZ) * 4)   // 89088 B

__global__ __launch_bounds__(128) void attn_tf32_kernel()
{
    extern __shared__ float sm[];
    float* Ks[2] = { sm,            sm + KSZ + VSZ };
    float* Vs[2] = { sm + KSZ,      sm + 2 * KSZ + VSZ };
    float* QP    = sm + 2 * (KSZ + VSZ);

    const int tid  = threadIdx.x;
    const int lane = tid & 31;
    const int warp = tid >> 5;
    const int r    = lane >> 2;
    const int cq   = lane & 3;
    const int bq   = gridDim.x - 1 - blockIdx.x;
    const int h    = blockIdx.y;
    const int b    = blockIdx.z;
    const int qbase = bq * 64;

    const int lrow = tid >> 4;
    const int lcol = (tid & 15) * 4;

    {
        #pragma unroll
        for (int i = 0; i < 8; ++i) {
            int row = lrow + i * 8;
            size_t g = ((size_t)(b * S_LEN + row)) * EMB + h * HD + lcol;
            cp16(&Ks[0][row * KSTR + lcol], &g_k[g]);
            cp16(&Vs[0][row * VSTR + lcol], &g_v[g]);
        }
        CP_COMMIT();
    }

    #pragma unroll
    for (int i = 0; i < 8; ++i) {
        int row = lrow + i * 8;
        *(float4*)&QP[row * KSTR + lcol] =
            *(const float4*)&g_q[((size_t)(b * S_LEN + qbase + row)) * EMB + h * HD + lcol];
    }
    __syncthreads();

    uint32_t qf[8][4];
    {
        int row0 = warp * 16 + r;
        #pragma unroll
        for (int ks = 0; ks < 8; ++ks) {
            int kc = ks * 8 + cq;
            qf[ks][0] = tf32_rna(QP[row0 * KSTR + kc] * 0.125f);
            qf[ks][1] = tf32_rna(QP[(row0 + 8) * KSTR + kc] * 0.125f);
            qf[ks][2] = tf32_rna(QP[row0 * KSTR + kc + 4] * 0.125f);
            qf[ks][3] = tf32_rna(QP[(row0 + 8) * KSTR + kc + 4] * 0.125f);
        }
    }
    __syncthreads();

    float o[8][4];
    #pragma unroll
    for (int nt = 0; nt < 8; ++nt)
        #pragma unroll
        for (int i = 0; i < 4; ++i) o[nt][i] = 0.f;
    float m0 = -1e30f, m1 = -1e30f, l0 = 0.f, l1 = 0.f;

    const int qr0 = warp * 16 + r;
    const int qr1 = qr0 + 8;

    for (int kb = 0; kb <= bq; ++kb) {
        const int cur = kb & 1;
        if (kb < bq) {
            float* Kn = Ks[cur ^ 1];
            float* Vn = Vs[cur ^ 1];
            #pragma unroll
            for (int i = 0; i < 8; ++i) {
                int row = lrow + i * 8;
                size_t g = ((size_t)(b * S_LEN + (kb + 1) * 64 + row)) * EMB + h * HD + lcol;
                cp16(&Kn[row * KSTR + lcol], &g_k[g]);
                cp16(&Vn[row * VSTR + lcol], &g_v[g]);
            }
        }
        CP_COMMIT();
        CP_WAIT1();
        __syncthreads();

        const float* Kc = Ks[cur];
        const float* Vc = Vs[cur];

        float s[8][4];
        #pragma unroll
        for (int nt = 0; nt < 8; ++nt)
            #pragma unroll
            for (int i = 0; i < 4; ++i) s[nt][i] = 0.f;
        #pragma unroll
        for (int ks = 0; ks < 8; ++ks) {
            int kc = ks * 8 + cq;
            #pragma unroll
            for (int nt = 0; nt < 8; ++nt) {
                int krow = nt * 8 + r;
                uint32_t b0 = tf32_rna(Kc[krow * KSTR + kc]);
                uint32_t b1 = tf32_rna(Kc[krow * KSTR + kc + 4]);
                mma_tf32(s[nt], qf[ks][0], qf[ks][1], qf[ks][2], qf[ks][3], b0, b1);
            }
        }

        if (kb == bq) {
            #pragma unroll
            for (int nt = 0; nt < 8; ++nt) {
                int kc = nt * 8 + 2 * cq;
                if (kc     > qr0) s[nt][0] = -1e30f;
                if (kc + 1 > qr0) s[nt][1] = -1e30f;
                if (kc     > qr1) s[nt][2] = -1e30f;
                if (kc + 1 > qr1) s[nt][3] = -1e30f;
            }
        }

        float mx0 = -1e30f, mx1 = -1e30f;
        #pragma unroll
        for (int nt = 0; nt < 8; ++nt) {
            mx0 = fmaxf(mx0, fmaxf(s[nt][0], s[nt][1]));
            mx1 = fmaxf(mx1, fmaxf(s[nt][2], s[nt][3]));
        }
        mx0 = fmaxf(mx0, __shfl_xor_sync(0xffffffffu, mx0, 1));
        mx0 = fmaxf(mx0, __shfl_xor_sync(0xffffffffu, mx0, 2));
        mx1 = fmaxf(mx1, __shfl_xor_sync(0xffffffffu, mx1, 1));
        mx1 = fmaxf(mx1, __shfl_xor_sync(0xffffffffu, mx1, 2));
        float mn0 = fmaxf(m0, mx0), mn1 = fmaxf(m1, mx1);
        float sc0 = __expf(m0 - mn0), sc1 = __expf(m1 - mn1);
        m0 = mn0; m1 = mn1;
        float ls0 = 0.f, ls1 = 0.f;
        #pragma unroll
        for (int nt = 0; nt < 8; ++nt) {
            s[nt][0] = __expf(s[nt][0] - m0);
            s[nt][1] = __expf(s[nt][1] - m0);
            s[nt][2] = __expf(s[nt][2] - m1);
            s[nt][3] = __expf(s[nt][3] - m1);
            ls0 += s[nt][0] + s[nt][1];
            ls1 += s[nt][2] + s[nt][3];
        }
        ls0 += __shfl_xor_sync(0xffffffffu, ls0, 1);
        ls0 += __shfl_xor_sync(0xffffffffu, ls0, 2);
        ls1 += __shfl_xor_sync(0xffffffffu, ls1, 1);
        ls1 += __shfl_xor_sync(0xffffffffu, ls1, 2);
        l0 = l0 * sc0 + ls0;
        l1 = l1 * sc1 + ls1;
        #pragma unroll
        for (int nt = 0; nt < 8; ++nt) {
            o[nt][0] *= sc0; o[nt][1] *= sc0;
            o[nt][2] *= sc1; o[nt][3] *= sc1;
        }

        #pragma unroll
        for (int nt = 0; nt < 8; ++nt) {
            int kc = nt * 8 + 2 * cq;
            QP[qr0 * KSTR + kc]     = s[nt][0];
            QP[qr0 * KSTR + kc + 1] = s[nt][1];
            QP[qr1 * KSTR + kc]     = s[nt][2];
            QP[qr1 * KSTR + kc + 1] = s[nt][3];
        }
        __syncwarp();

        #pragma unroll
        for (int kv = 0; kv < 8; ++kv) {
            int kc = kv * 8 + cq;
            uint32_t p0 = tf32_rna(QP[qr0 * KSTR + kc]);
            uint32_t p1 = tf32_rna(QP[qr1 * KSTR + kc]);
            uint32_t p2 = tf32_rna(QP[qr0 * KSTR + kc + 4]);
            uint32_t p3 = tf32_rna(QP[qr1 * KSTR + kc + 4]);
            #pragma unroll
            for (int nt = 0; nt < 8; ++nt) {
                int ncol = nt * 8 + r;
                uint32_t b0 = tf32_rna(Vc[(kv * 8 + cq) * VSTR + ncol]);
                uint32_t b1 = tf32_rna(Vc[(kv * 8 + cq + 4) * VSTR + ncol]);
                mma_tf32(o[nt], p0, p1, p2, p3, b0, b1);
            }
        }
        __syncthreads();
    }

    float inv0 = 1.f / l0, inv1 = 1.f / l1;
    #pragma unroll
    for (int nt = 0; nt < 8; ++nt) {
        int col = h * HD + nt * 8 + 2 * cq;
        float2 v0 = make_float2(o[nt][0] * inv0, o[nt][1] * inv0);
        float2 v1 = make_float2(o[nt][2] * inv1, o[nt][3] * inv1);
        *(float2*)&g_att[((size_t)(b * S_LEN + qbase + qr0)) * EMB + col] = v0;
        *(float2*)&g_att[((size_t)(b * S_LEN + qbase + qr1)) * EMB + col] = v1;
    }
}

// ---------------------------------------------------------------------------
extern "C" void kernel_launch(void* const* d_in, const int* in_sizes, int n_in,
                              void* d_out, int out_size)
{
    const float* x  = (const float*)d_in[0];
    const float* Wq = (const float*)d_in[1];
    const float* Wk = (const float*)d_in[2];
    const float* Wv = (const float*)d_in[3];
    const float* Wp = (const float*)d_in[4];
    const float* bp = (const float*)d_in[5];
    float* out = (float*)d_out;

    uint32_t *xh, *xl, *ath, *atl;
    float* att;
    cudaGetSymbolAddress((void**)&xh,  g_xh);
    cudaGetSymbolAddress((void**)&xl,  g_xl);
    cudaGetSymbolAddress((void**)&ath, g_ath);
    cudaGetSymbolAddress((void**)&atl, g_atl);
    cudaGetSymbolAddress((void**)&att, g_att);

    cudaFuncSetAttribute(qkv_gemm_kernel,  cudaFuncAttributeMaxDynamicSharedMemorySize, GEMM_SMEM);
    cudaFuncSetAttribute(proj_gemm_kernel, cudaFuncAttributeMaxDynamicSharedMemorySize, GEMM_SMEM);
    cudaFuncSetAttribute(attn_tf32_kernel, cudaFuncAttributeMaxDynamicSharedMemorySize, ATTN_SMEM);

    // Pre-split inputs (x and the 4 weight matrices) into tiled bf16x2 hi/lo.
    split_a_kernel<<<dim3(32, 32), 256>>>(x, xh, xl);
    split_w_kernel<<<dim3(32, 8, 4), 256>>>(Wq, Wk, Wv, Wp);

    // QKV projections (3 GEMMs fused via z).
    qkv_gemm_kernel<<<dim3(8, 32, 3), 512, GEMM_SMEM>>>();

    // Attention.
    attn_tf32_kernel<<<dim3(S_LEN / 64, NH, BATCH), 128, ATTN_SMEM>>>();

    // Split attention output for the projection GEMM.
    split_a_kernel<<<dim3(32, 32), 256>>>(att, ath, atl);

    // Output projection (+bias).
    proj_gemm_kernel<<<dim3(8, 32), 512, GEMM_SMEM>>>(out, bp);
}

// round 14
// speedup vs baseline: 1.8717x; 1.0577x over previous
#include <cuda_runtime.h>
#include <cuda_bf16.h>
#include <math.h>
#include <stdint.h>
#include <string.h>

#define S_LEN 2048
#define BATCH 2
#define EMB   1024
#define NH    16
#define HD    64
#define MTOT  (BATCH * S_LEN)   // 4096

// fp32 intermediates (g_q/g_k/g_v hold tf32-rounded values)
__device__ float g_q[MTOT * EMB];
__device__ float g_k[MTOT * EMB];
__device__ float g_v[MTOT * EMB];
__device__ float g_att[MTOT * EMB];

// Pre-split tiled bf16x2 buffers.
#define TILE_U32 2176                       // 16 pairs * 136
#define ATILES_U32 (32 * 32 * TILE_U32)
#define BTILES_U32 (8 * 32 * TILE_U32)
__device__ uint32_t g_xh[ATILES_U32],  g_xl[ATILES_U32];
__device__ uint32_t g_ath[ATILES_U32], g_atl[ATILES_U32];
__device__ uint32_t g_wh[4][BTILES_U32], g_wl[4][BTILES_U32];   // q,k,v,p

// ---- helpers --------------------------------------------------------------
__device__ __forceinline__ void mma_bf16(float c[4], uint32_t a0, uint32_t a1,
                                         uint32_t a2, uint32_t a3,
                                         uint32_t b0, uint32_t b1)
{
    asm volatile(
        "mma.sync.aligned.m16n8k16.row.col.f32.bf16.bf16.f32 "
        "{%0,%1,%2,%3}, {%4,%5,%6,%7}, {%8,%9}, {%0,%1,%2,%3};"
        : "+f"(c[0]), "+f"(c[1]), "+f"(c[2]), "+f"(c[3])
        : "r"(a0), "r"(a1), "r"(a2), "r"(a3), "r"(b0), "r"(b1));
}
__device__ __forceinline__ void mma_tf32(float c[4], uint32_t a0, uint32_t a1,
                                         uint32_t a2, uint32_t a3,
                                         uint32_t b0, uint32_t b1)
{
    asm volatile(
        "mma.sync.aligned.m16n8k8.row.col.f32.tf32.tf32.f32 "
        "{%0,%1,%2,%3}, {%4,%5,%6,%7}, {%8,%9}, {%0,%1,%2,%3};"
        : "+f"(c[0]), "+f"(c[1]), "+f"(c[2]), "+f"(c[3])
        : "r"(a0), "r"(a1), "r"(a2), "r"(a3), "r"(b0), "r"(b1));
}
__device__ __forceinline__ uint32_t tf32_rna(float x)
{
    uint32_t r;
    asm("cvt.rna.tf32.f32 %0, %1;" : "=r"(r) : "f"(x));
    return r;
}
__device__ __forceinline__ uint32_t f2b(float x) { return __float_as_uint(x); }

__device__ __forceinline__ uint32_t pack_hi2(float a, float b, float& ra, float& rb)
{
    __nv_bfloat162 h = __floats2bfloat162_rn(a, b);
    ra = a - __bfloat162float(h.x);
    rb = b - __bfloat162float(h.y);
    uint32_t u; memcpy(&u, &h, 4); return u;
}
__device__ __forceinline__ uint32_t pack_lo2(float ra, float rb)
{
    __nv_bfloat162 l = __floats2bfloat162_rn(ra, rb);
    uint32_t u; memcpy(&u, &l, 4); return u;
}
__device__ __forceinline__ void cp16(void* smem, const void* gmem)
{
    uint32_t s = (uint32_t)__cvta_generic_to_shared(smem);
    asm volatile("cp.async.cg.shared.global [%0], [%1], 16;" :: "r"(s), "l"(gmem));
}
#define CP_COMMIT() asm volatile("cp.async.commit_group;" ::: "memory")
#define CP_WAIT0()  asm volatile("cp.async.wait_group 0;" ::: "memory")
#define CP_WAIT1()  asm volatile("cp.async.wait_group 1;" ::: "memory")

// ---------------------------------------------------------------------------
// Split kernels: fp32 -> tiled pair-packed bf16x2 hi/lo.
// ---------------------------------------------------------------------------
__global__ __launch_bounds__(256) void split_a_kernel(
    const float* __restrict__ src, uint32_t* __restrict__ dh, uint32_t* __restrict__ dl)
{
    __shared__ float s[128 * 33];
    const int kt = blockIdx.x, mb = blockIdx.y;
    const int t = threadIdx.x;
    {
        int row = t >> 1, half = (t & 1) * 16;
        const float* sp = src + (size_t)(mb * 128 + row) * EMB + kt * 32 + half;
        #pragma unroll
        for (int j = 0; j < 4; ++j) {
            float4 v = *(const float4*)(sp + j * 4);
            s[row * 33 + half + j * 4 + 0] = v.x;
            s[row * 33 + half + j * 4 + 1] = v.y;
            s[row * 33 + half + j * 4 + 2] = v.z;
            s[row * 33 + half + j * 4 + 3] = v.w;
        }
    }
    __syncthreads();
    size_t off = (size_t)(mb * 32 + kt) * TILE_U32;
    for (int idx = t; idx < TILE_U32; idx += 256) {
        int pa = idx / 136, rw = idx - pa * 136;
        uint32_t h = 0, l = 0;
        if (rw < 128) {
            float a = s[rw * 33 + 2 * pa], b = s[rw * 33 + 2 * pa + 1];
            float ra, rb;
            h = pack_hi2(a, b, ra, rb);
            l = pack_lo2(ra, rb);
        }
        dh[off + idx] = h;
        dl[off + idx] = l;
    }
}

__global__ __launch_bounds__(256) void split_w_kernel(
    const float* __restrict__ Wq, const float* __restrict__ Wk,
    const float* __restrict__ Wv, const float* __restrict__ Wp)
{
    __shared__ float s[32 * 129];
    const int kt = blockIdx.x, nb = blockIdx.y, z = blockIdx.z;
    const float* src = (z == 0) ? Wq : (z == 1) ? Wk : (z == 2) ? Wv : Wp;
    const int t = threadIdx.x;
    {
        int row = t >> 3, off8 = (t & 7) * 16;
        const float* sp = src + (size_t)(kt * 32 + row) * EMB + nb * 128 + off8;
        #pragma unroll
        for (int j = 0; j < 4; ++j) {
            float4 v = *(const float4*)(sp + j * 4);
            s[row * 129 + off8 + j * 4 + 0] = v.x;
            s[row * 129 + off8 + j * 4 + 1] = v.y;
            s[row * 129 + off8 + j * 4 + 2] = v.z;
            s[row * 129 + off8 + j * 4 + 3] = v.w;
        }
    }
    __syncthreads();
    size_t off = (size_t)(nb * 32 + kt) * TILE_U32;
    uint32_t* dh = g_wh[z];
    uint32_t* dl = g_wl[z];
    for (int idx = t; idx < TILE_U32; idx += 256) {
        int pi = idx / 136, n = idx - pi * 136;
        uint32_t h = 0, l = 0;
        if (n < 128) {
            float a = s[(2 * pi) * 129 + n], b = s[(2 * pi + 1) * 129 + n];
            float ra, rb;
            h = pack_hi2(a, b, ra, rb);
            l = pack_lo2(ra, rb);
        }
        dh[off + idx] = h;
        dl[off + idx] = l;
    }
}

// ---------------------------------------------------------------------------
// 3xBF16 GEMM from pre-split tiles, 3-stage cp.async pipeline.
// round_out != 0: store tf32-rna-rounded results (for q/k/v feeding attention).
// ---------------------------------------------------------------------------
#define STG_U32 (4 * TILE_U32)
#define GEMM_SMEM (3 * STG_U32 * 4)            // 104448 B
#define NKT 32

__device__ __forceinline__ void gemm3_body(
    const uint32_t* __restrict__ Ah, const uint32_t* __restrict__ Al,
    const uint32_t* __restrict__ Bh, const uint32_t* __restrict__ Bl,
    const float* __restrict__ bias, float* __restrict__ C, int round_out)
{
    extern __shared__ uint32_t usm[];

    const int tid   = threadIdx.x;
    const int lane  = tid & 31;
    const int warp  = tid >> 5;
    const int warpM = warp >> 2;
    const int warpN = warp & 3;
    const int r     = lane >> 2;
    const int cq    = lane & 3;
    const int nb    = blockIdx.x;
    const int mb    = blockIdx.y;
    const size_t aBase = (size_t)mb * 32 * TILE_U32;
    const size_t bBase = (size_t)nb * 32 * TILE_U32;

    float acc[2][4][4];
    #pragma unroll
    for (int mt = 0; mt < 2; ++mt)
        #pragma unroll
        for (int nt = 0; nt < 4; ++nt)
            #pragma unroll
            for (int i = 0; i < 4; ++i) acc[mt][nt][i] = 0.f;

    #define ISSUE(kt_)                                                          \
    {                                                                           \
        uint32_t* dst = usm + ((kt_) % 3) * STG_U32;                            \
        const uint32_t* sah = Ah + aBase + (size_t)(kt_) * TILE_U32;            \
        const uint32_t* sal = Al + aBase + (size_t)(kt_) * TILE_U32;            \
        const uint32_t* sbh = Bh + bBase + (size_t)(kt_) * TILE_U32;            \
        const uint32_t* sbl = Bl + bBase + (size_t)(kt_) * TILE_U32;            \
        for (int c = tid; c < 544; c += 512) {                                  \
            cp16(dst + c * 4,                sah + c * 4);                      \
            cp16(dst + TILE_U32 + c * 4,     sal + c * 4);                      \
            cp16(dst + 2 * TILE_U32 + c * 4, sbh + c * 4);                      \
            cp16(dst + 3 * TILE_U32 + c * 4, sbl + c * 4);                      \
        }                                                                       \
    }

    ISSUE(0) CP_COMMIT();
    ISSUE(1) CP_COMMIT();

    for (int kt = 0; kt < NKT; ++kt) {
        if (kt + 2 < NKT) CP_WAIT1(); else CP_WAIT0();
        __syncthreads();
        if (kt + 2 < NKT) { ISSUE(kt + 2) CP_COMMIT(); }

        const uint32_t* Ahs = usm + (kt % 3) * STG_U32;
        const uint32_t* Als = Ahs + TILE_U32;
        const uint32_t* Bhs = Ahs + 2 * TILE_U32;
        const uint32_t* Bls = Ahs + 3 * TILE_U32;

        #pragma unroll
        for (int ks = 0; ks < 2; ++ks) {
            uint32_t ah[2][4], al[2][4];
            #pragma unroll
            for (int mt = 0; mt < 2; ++mt) {
                int row0 = warpM * 32 + mt * 16 + r;
                int pa   = ks * 8 + cq;
                ah[mt][0] = Ahs[pa * 136 + row0];
                ah[mt][1] = Ahs[pa * 136 + row0 + 8];
                ah[mt][2] = Ahs[(pa + 4) * 136 + row0];
                ah[mt][3] = Ahs[(pa + 4) * 136 + row0 + 8];
                al[mt][0] = Als[pa * 136 + row0];
                al[mt][1] = Als[pa * 136 + row0 + 8];
                al[mt][2] = Als[(pa + 4) * 136 + row0];
                al[mt][3] = Als[(pa + 4) * 136 + row0 + 8];
            }
            #pragma unroll
            for (int nt = 0; nt < 4; ++nt) {
                int ncol = warpN * 32 + nt * 8 + r;
                uint32_t bh0 = Bhs[(ks * 8 + cq) * 136 + ncol];
                uint32_t bh1 = Bhs[(ks * 8 + cq + 4) * 136 + ncol];
                uint32_t bl0 = Bls[(ks * 8 + cq) * 136 + ncol];
                uint32_t bl1 = Bls[(ks * 8 + cq + 4) * 136 + ncol];
                #pragma unroll
                for (int mt = 0; mt < 2; ++mt) {
                    mma_bf16(acc[mt][nt], ah[mt][0], ah[mt][1], ah[mt][2], ah[mt][3], bl0, bl1);
                    mma_bf16(acc[mt][nt], al[mt][0], al[mt][1], al[mt][2], al[mt][3], bh0, bh1);
                    mma_bf16(acc[mt][nt], ah[mt][0], ah[mt][1], ah[mt][2], ah[mt][3], bh0, bh1);
                }
            }
        }
    }
    #undef ISSUE

    #pragma unroll
    for (int mt = 0; mt < 2; ++mt) {
        int row = mb * 128 + warpM * 32 + mt * 16 + r;
        #pragma unroll
        for (int nt = 0; nt < 4; ++nt) {
            int col = nb * 128 + warpN * 32 + nt * 8 + 2 * cq;
            float b0 = 0.f, b1 = 0.f;
            if (bias) { b0 = bias[col]; b1 = bias[col + 1]; }
            float v00 = acc[mt][nt][0] + b0, v01 = acc[mt][nt][1] + b1;
            float v10 = acc[mt][nt][2] + b0, v11 = acc[mt][nt][3] + b1;
            if (round_out) {
                v00 = __uint_as_float(tf32_rna(v00));
                v01 = __uint_as_float(tf32_rna(v01));
                v10 = __uint_as_float(tf32_rna(v10));
                v11 = __uint_as_float(tf32_rna(v11));
            }
            *(float2*)&C[(size_t)row * EMB + col]       = make_float2(v00, v01);
            *(float2*)&C[(size_t)(row + 8) * EMB + col] = make_float2(v10, v11);
        }
    }
}

__global__ __launch_bounds__(512) void qkv_gemm_kernel()
{
    const int z = blockIdx.z;
    float* C = (z == 0) ? g_q : (z == 1) ? g_k : g_v;
    gemm3_body(g_xh, g_xl, g_wh[z], g_wl[z], nullptr, C, 1);
}

__global__ __launch_bounds__(512) void proj_gemm_kernel(float* __restrict__ out,
                                                        const float* __restrict__ bias)
{
    gemm3_body(g_ath, g_atl, g_wh[3], g_wl[3], bias, out, 0);
}

// ---------------------------------------------------------------------------
// 1xTF32 flash attention. Q/K/V are PRE-ROUNDED to tf32 by the QKV epilogue,
// so the mainloop has zero cvt.rna on the K/V/Q paths (bit patterns used
// directly). 128 threads, 64 q/CTA, cp.async double-buffered K/V tiles.
// ---------------------------------------------------------------------------
#define KSTR 68
#define VSTR 72
#define KSZ (64 * KSTR)
#define VSZ (64 * VSTR)
#define ATTN_SMEM ((2 * (KSZ + VSZ) + KSZ) * 4)   // 89088 B

__global__ __launch_bounds__(128) void attn_tf32_kernel()
{
    extern __shared__ float sm[];
    float* Ks[2] = { sm,            sm + KSZ + VSZ };
    float* Vs[2] = { sm + KSZ,      sm + 2 * KSZ + VSZ };
    float* QP    = sm + 2 * (KSZ + VSZ);

    const int tid  = threadIdx.x;
    const int lane = tid & 31;
    const int warp = tid >> 5;
    const int r    = lane >> 2;
    const int cq   = lane & 3;
    const int bq   = gridDim.x - 1 - blockIdx.x;
    const int h    = blockIdx.y;
    const int b    = blockIdx.z;
    const int qbase = bq * 64;

    const int lrow = tid >> 4;
    const int lcol = (tid & 15) * 4;

    {
        #pragma unroll
        for (int i = 0; i < 8; ++i) {
            int row = lrow + i * 8;
            size_t g = ((size_t)(b * S_LEN + row)) * EMB + h * HD + lcol;
            cp16(&Ks[0][row * KSTR + lcol], &g_k[g]);
            cp16(&Vs[0][row * VSTR + lcol], &g_v[g]);
        }
        CP_COMMIT();
    }

    #pragma unroll
    for (int i = 0; i < 8; ++i) {
        int row = lrow + i * 8;
        *(float4*)&QP[row * KSTR + lcol] =
            *(const float4*)&g_q[((size_t)(b * S_LEN + qbase + row)) * EMB + h * HD + lcol];
    }
    __syncthreads();

    // Q is tf32 already; *0.125 (exact power of 2) keeps it tf32.
    uint32_t qf[8][4];
    {
        int row0 = warp * 16 + r;
        #pragma unroll
        for (int ks = 0; ks < 8; ++ks) {
            int kc = ks * 8 + cq;
            qf[ks][0] = f2b(QP[row0 * KSTR + kc] * 0.125f);
            qf[ks][1] = f2b(QP[(row0 + 8) * KSTR + kc] * 0.125f);
            qf[ks][2] = f2b(QP[row0 * KSTR + kc + 4] * 0.125f);
            qf[ks][3] = f2b(QP[(row0 + 8) * KSTR + kc + 4] * 0.125f);
        }
    }
    __syncthreads();

    float o[8][4];
    #pragma unroll
    for (int nt = 0; nt < 8; ++nt)
        #pragma unroll
        for (int i = 0; i < 4; ++i) o[nt][i] = 0.f;
    float m0 = -1e30f, m1 = -1e30f, l0 = 0.f, l1 = 0.f;

    const int qr0 = warp * 16 + r;
    const int qr1 = qr0 + 8;

    for (int kb = 0; kb <= bq; ++kb) {
        const int cur = kb & 1;
        if (kb < bq) {
            float* Kn = Ks[cur ^ 1];
            float* Vn = Vs[cur ^ 1];
            #pragma unroll
            for (int i = 0; i < 8; ++i) {
                int row = lrow + i * 8;
                size_t g = ((size_t)(b * S_LEN + (kb + 1) * 64 + row)) * EMB + h * HD + lcol;
                cp16(&Kn[row * KSTR + lcol], &g_k[g]);
                cp16(&Vn[row * VSTR + lcol], &g_v[g]);
            }
        }
        CP_COMMIT();
        CP_WAIT1();
        __syncthreads();

        const float* Kc = Ks[cur];
        const float* Vc = Vs[cur];

        // S = (Q/8) @ K^T — K already tf32, raw bit loads
        float s[8][4];
        #pragma unroll
        for (int nt = 0; nt < 8; ++nt)
            #pragma unroll
            for (int i = 0; i < 4; ++i) s[nt][i] = 0.f;
        #pragma unroll
        for (int ks = 0; ks < 8; ++ks) {
            int kc = ks * 8 + cq;
            #pragma unroll
            for (int nt = 0; nt < 8; ++nt) {
                int krow = nt * 8 + r;
                uint32_t b0 = f2b(Kc[krow * KSTR + kc]);
                uint32_t b1 = f2b(Kc[krow * KSTR + kc + 4]);
                mma_tf32(s[nt], qf[ks][0], qf[ks][1], qf[ks][2], qf[ks][3], b0, b1);
            }
        }

        if (kb == bq) {
            #pragma unroll
            for (int nt = 0; nt < 8; ++nt) {
                int kc = nt * 8 + 2 * cq;
                if (kc     > qr0) s[nt][0] = -1e30f;
                if (kc + 1 > qr0) s[nt][1] = -1e30f;
                if (kc     > qr1) s[nt][2] = -1e30f;
                if (kc + 1 > qr1) s[nt][3] = -1e30f;
            }
        }

        float mx0 = -1e30f, mx1 = -1e30f;
        #pragma unroll
        for (int nt = 0; nt < 8; ++nt) {
            mx0 = fmaxf(mx0, fmaxf(s[nt][0], s[nt][1]));
            mx1 = fmaxf(mx1, fmaxf(s[nt][2], s[nt][3]));
        }
        mx0 = fmaxf(mx0, __shfl_xor_sync(0xffffffffu, mx0, 1));
        mx0 = fmaxf(mx0, __shfl_xor_sync(0xffffffffu, mx0, 2));
        mx1 = fmaxf(mx1, __shfl_xor_sync(0xffffffffu, mx1, 1));
        mx1 = fmaxf(mx1, __shfl_xor_sync(0xffffffffu, mx1, 2));
        float mn0 = fmaxf(m0, mx0), mn1 = fmaxf(m1, mx1);
        float sc0 = __expf(m0 - mn0), sc1 = __expf(m1 - mn1);
        m0 = mn0; m1 = mn1;
        float ls0 = 0.f, ls1 = 0.f;
        #pragma unroll
        for (int nt = 0; nt < 8; ++nt) {
            s[nt][0] = __expf(s[nt][0] - m0);
            s[nt][1] = __expf(s[nt][1] - m0);
            s[nt][2] = __expf(s[nt][2] - m1);
            s[nt][3] = __expf(s[nt][3] - m1);
            ls0 += s[nt][0] + s[nt][1];
            ls1 += s[nt][2] + s[nt][3];
        }
        ls0 += __shfl_xor_sync(0xffffffffu, ls0, 1);
        ls0 += __shfl_xor_sync(0xffffffffu, ls0, 2);
        ls1 += __shfl_xor_sync(0xffffffffu, ls1, 1);
        ls1 += __shfl_xor_sync(0xffffffffu, ls1, 2);
        l0 = l0 * sc0 + ls0;
        l1 = l1 * sc1 + ls1;
        #pragma unroll
        for (int nt = 0; nt < 8; ++nt) {
            o[nt][0] *= sc0; o[nt][1] *= sc0;
            o[nt][2] *= sc1; o[nt][3] *= sc1;
        }

        #pragma unroll
        for (int nt = 0; nt < 8; ++nt) {
            int kc = nt * 8 + 2 * cq;
            QP[qr0 * KSTR + kc]     = s[nt][0];
            QP[qr0 * KSTR + kc + 1] = s[nt][1];
            QP[qr1 * KSTR + kc]     = s[nt][2];
            QP[qr1 * KSTR + kc + 1] = s[nt][3];
        }
        __syncwarp();

        // O += P @ V — P needs rna (post-exp); V already tf32.
        #pragma unroll
        for (int kv = 0; kv < 8; ++kv) {
            int kc = kv * 8 + cq;
            uint32_t p0 = tf32_rna(QP[qr0 * KSTR + kc]);
            uint32_t p1 = tf32_rna(QP[qr1 * KSTR + kc]);
            uint32_t p2 = tf32_rna(QP[qr0 * KSTR + kc + 4]);
            uint32_t p3 = tf32_rna(QP[qr1 * KSTR + kc + 4]);
            #pragma unroll
            for (int nt = 0; nt < 8; ++nt) {
                int ncol = nt * 8 + r;
                uint32_t b0 = f2b(Vc[(kv * 8 + cq) * VSTR + ncol]);
                uint32_t b1 = f2b(Vc[(kv * 8 + cq + 4) * VSTR + ncol]);
                mma_tf32(o[nt], p0, p1, p2, p3, b0, b1);
            }
        }
        __syncthreads();
    }

    float inv0 = 1.f / l0, inv1 = 1.f / l1;
    #pragma unroll
    for (int nt = 0; nt < 8; ++nt) {
        int col = h * HD + nt * 8 + 2 * cq;
        float2 v0 = make_float2(o[nt][0] * inv0, o[nt][1] * inv0);
        float2 v1 = make_float2(o[nt][2] * inv1, o[nt][3] * inv1);
        *(float2*)&g_att[((size_t)(b * S_LEN + qbase + qr0)) * EMB + col] = v0;
        *(float2*)&g_att[((size_t)(b * S_LEN + qbase + qr1)) * EMB + col] = v1;
    }
}

// ---------------------------------------------------------------------------
extern "C" void kernel_launch(void* const* d_in, const int* in_sizes, int n_in,
                              void* d_out, int out_size)
{
    const float* x  = (const float*)d_in[0];
    const float* Wq = (const float*)d_in[1];
    const float* Wk = (const float*)d_in[2];
    const float* Wv = (const float*)d_in[3];
    const float* Wp = (const float*)d_in[4];
    const float* bp = (const float*)d_in[5];
    float* out = (float*)d_out;

    uint32_t *xh, *xl, *ath, *atl;
    float* att;
    cudaGetSymbolAddress((void**)&xh,  g_xh);
    cudaGetSymbolAddress((void**)&xl,  g_xl);
    cudaGetSymbolAddress((void**)&ath, g_ath);
    cudaGetSymbolAddress((void**)&atl, g_atl);
    cudaGetSymbolAddress((void**)&att, g_att);

    cudaFuncSetAttribute(qkv_gemm_kernel,  cudaFuncAttributeMaxDynamicSharedMemorySize, GEMM_SMEM);
    cudaFuncSetAttribute(proj_gemm_kernel, cudaFuncAttributeMaxDynamicSharedMemorySize, GEMM_SMEM);
    cudaFuncSetAttribute(attn_tf32_kernel, cudaFuncAttributeMaxDynamicSharedMemorySize, ATTN_SMEM);

    split_a_kernel<<<dim3(32, 32), 256>>>(x, xh, xl);
    split_w_kernel<<<dim3(32, 8, 4), 256>>>(Wq, Wk, Wv, Wp);

    qkv_gemm_kernel<<<dim3(8, 32, 3), 512, GEMM_SMEM>>>();

    attn_tf32_kernel<<<dim3(S_LEN / 64, NH, BATCH), 128, ATTN_SMEM>>>();

    split_a_kernel<<<dim3(32, 32), 256>>>(att, ath, atl);

    proj_gemm_kernel<<<dim3(8, 32), 512, GEMM_SMEM>>>(out, bp);
}